// round 1
// baseline (speedup 1.0000x reference)
#include <cuda_runtime.h>
#include <math.h>

#define BB     4
#define SEQ    2048
#define DIMD   1024
#define HEADS  16
#define DH     64
#define ROT    32
#define BH     (BB*HEADS)          // 64
#define MROWS  (BB*SEQ)            // 8192
#define OUT_ELEMS ((size_t)MROWS*DIMD)   // 8388608

// ---------------- scratch (device globals: allocation-free) ----------------
__device__ float g_Q[(size_t)BH*SEQ*DH];
__device__ float g_K[(size_t)BH*SEQ*DH];
__device__ float g_V[(size_t)BH*SEQ*DH];
__device__ float g_O[(size_t)MROWS*DIMD];

// ---------------- 128x128 fp32 GEMM: Y(head-major) = X @ W ----------------
// X: [8192,1024] row-major, W: [1024,1024] row-major.
// Output permuted to [b,h,n,d] with c = h*64+d, m = b*2048+n.
__global__ void proj_gemm(const float* __restrict__ X, const float* __restrict__ W,
                          float* __restrict__ Y) {
    __shared__ float As[8][128];
    __shared__ float Bs[8][128];
    int tid = threadIdx.x;
    int tx = tid & 15, ty = tid >> 4;
    int row0 = blockIdx.y * 128;
    int col0 = blockIdx.x * 128;

    float acc[8][8];
#pragma unroll
    for (int i = 0; i < 8; i++)
#pragma unroll
        for (int j = 0; j < 8; j++) acc[i][j] = 0.f;

    int am = tid >> 1;           // 0..127
    int ak = (tid & 1) * 4;      // 0 or 4
    int bk = tid >> 5;           // 0..7
    int bc = (tid & 31) * 4;     // 0..124

    for (int k0 = 0; k0 < DIMD; k0 += 8) {
        float4 a = *(const float4*)(X + (size_t)(row0 + am) * DIMD + k0 + ak);
        As[ak + 0][am] = a.x; As[ak + 1][am] = a.y;
        As[ak + 2][am] = a.z; As[ak + 3][am] = a.w;
        float4 b = *(const float4*)(W + (size_t)(k0 + bk) * DIMD + col0 + bc);
        *(float4*)&Bs[bk][bc] = b;
        __syncthreads();
#pragma unroll
        for (int kk = 0; kk < 8; kk++) {
            float4 a0 = *(float4*)&As[kk][ty * 4];
            float4 a1 = *(float4*)&As[kk][64 + ty * 4];
            float4 b0 = *(float4*)&Bs[kk][tx * 4];
            float4 b1 = *(float4*)&Bs[kk][64 + tx * 4];
            float av[8] = {a0.x, a0.y, a0.z, a0.w, a1.x, a1.y, a1.z, a1.w};
            float bw[8] = {b0.x, b0.y, b0.z, b0.w, b1.x, b1.y, b1.z, b1.w};
#pragma unroll
            for (int i = 0; i < 8; i++)
#pragma unroll
                for (int j = 0; j < 8; j++)
                    acc[i][j] = fmaf(av[i], bw[j], acc[i][j]);
        }
        __syncthreads();
    }

#pragma unroll
    for (int i = 0; i < 8; i++) {
        int m = row0 + (i < 4 ? ty * 4 + i : 64 + ty * 4 + i - 4);
        int bidx = m >> 11;        // /2048
        int n    = m & 2047;
#pragma unroll
        for (int j = 0; j < 8; j++) {
            int c = col0 + (j < 4 ? tx * 4 + j : 64 + tx * 4 + j - 4);
            int h = c >> 6, d = c & 63;
            Y[(((size_t)(bidx * HEADS + h) * SEQ + n) << 6) + d] = acc[i][j];
        }
    }
}

// ------------- final GEMM: out = g_O @ Wo + bo + x (residual) --------------
__global__ void final_gemm(const float* __restrict__ W, const float* __restrict__ bo,
                           const float* __restrict__ resid, float* __restrict__ out) {
    __shared__ float As[8][128];
    __shared__ float Bs[8][128];
    int tid = threadIdx.x;
    int tx = tid & 15, ty = tid >> 4;
    int row0 = blockIdx.y * 128;
    int col0 = blockIdx.x * 128;

    float acc[8][8];
#pragma unroll
    for (int i = 0; i < 8; i++)
#pragma unroll
        for (int j = 0; j < 8; j++) acc[i][j] = 0.f;

    int am = tid >> 1;
    int ak = (tid & 1) * 4;
    int bk = tid >> 5;
    int bc = (tid & 31) * 4;

    for (int k0 = 0; k0 < DIMD; k0 += 8) {
        float4 a = *(const float4*)(g_O + (size_t)(row0 + am) * DIMD + k0 + ak);
        As[ak + 0][am] = a.x; As[ak + 1][am] = a.y;
        As[ak + 2][am] = a.z; As[ak + 3][am] = a.w;
        float4 b = *(const float4*)(W + (size_t)(k0 + bk) * DIMD + col0 + bc);
        *(float4*)&Bs[bk][bc] = b;
        __syncthreads();
#pragma unroll
        for (int kk = 0; kk < 8; kk++) {
            float4 a0 = *(float4*)&As[kk][ty * 4];
            float4 a1 = *(float4*)&As[kk][64 + ty * 4];
            float4 b0 = *(float4*)&Bs[kk][tx * 4];
            float4 b1 = *(float4*)&Bs[kk][64 + tx * 4];
            float av[8] = {a0.x, a0.y, a0.z, a0.w, a1.x, a1.y, a1.z, a1.w};
            float bw[8] = {b0.x, b0.y, b0.z, b0.w, b1.x, b1.y, b1.z, b1.w};
#pragma unroll
            for (int i = 0; i < 8; i++)
#pragma unroll
                for (int j = 0; j < 8; j++)
                    acc[i][j] = fmaf(av[i], bw[j], acc[i][j]);
        }
        __syncthreads();
    }

#pragma unroll
    for (int i = 0; i < 8; i++) {
        int m = row0 + (i < 4 ? ty * 4 + i : 64 + ty * 4 + i - 4);
#pragma unroll
        for (int j = 0; j < 8; j++) {
            int c = col0 + (j < 4 ? tx * 4 + j : 64 + tx * 4 + j - 4);
            out[(size_t)m * DIMD + c] = acc[i][j] + bo[c] + resid[(size_t)m * DIMD + c];
        }
    }
}

// ---------------- partial RoPE on first 32 dims of q,k,v -------------------
__global__ void rope_kernel(const float* __restrict__ rope) {
    int idx = blockIdx.x * blockDim.x + threadIdx.x;   // BH*SEQ*16 threads
    if (idx >= BH * SEQ * 16) return;
    int p = idx & 15;
    int n = (idx >> 4) & (SEQ - 1);
    int z = idx >> 15;                                 // 16*2048 = 2^15
    size_t base = ((size_t)z * SEQ + n) * DH;
    float r1 = rope[n * ROT + p];
    float r2 = rope[n * ROT + p + 16];
    float c1 = cosf(r1), s1 = sinf(r1);
    float c2 = cosf(r2), s2 = sinf(r2);

    float* arrs[3] = {g_Q, g_K, g_V};
#pragma unroll
    for (int a = 0; a < 3; a++) {
        float t0 = arrs[a][base + p];
        float t1 = arrs[a][base + p + 16];
        arrs[a][base + p]      = t0 * c1 - t1 * s1;
        arrs[a][base + p + 16] = t1 * c2 + t0 * s2;
    }
}

// ---------------- S = scale * Q @ K^T, per (b,h) batch ---------------------
__global__ void qk_kernel(float* __restrict__ S) {
    __shared__ float Qs[64][65];
    __shared__ float Ks[64][65];
    int tid = threadIdx.x;
    int z  = blockIdx.z;
    int i0 = blockIdx.y * 64;
    int j0 = blockIdx.x * 64;
    const float* Qb = g_Q + (size_t)z * SEQ * DH;
    const float* Kb = g_K + (size_t)z * SEQ * DH;

#pragma unroll
    for (int t = 0; t < 4; t++) {
        int f = tid + t * 256;
        int r = f >> 4;
        int c = (f & 15) * 4;
        float4 qa = *(const float4*)(Qb + (size_t)(i0 + r) * DH + c);
        Qs[r][c] = qa.x; Qs[r][c+1] = qa.y; Qs[r][c+2] = qa.z; Qs[r][c+3] = qa.w;
        float4 ka = *(const float4*)(Kb + (size_t)(j0 + r) * DH + c);
        Ks[r][c] = ka.x; Ks[r][c+1] = ka.y; Ks[r][c+2] = ka.z; Ks[r][c+3] = ka.w;
    }
    __syncthreads();

    int ix = tid & 15, iy = tid >> 4;
    float acc[4][4] = {};
#pragma unroll 16
    for (int kk = 0; kk < 64; kk++) {
        float a[4], b[4];
#pragma unroll
        for (int r = 0; r < 4; r++) a[r] = Qs[iy * 4 + r][kk];
#pragma unroll
        for (int c = 0; c < 4; c++) b[c] = Ks[ix * 4 + c][kk];
#pragma unroll
        for (int r = 0; r < 4; r++)
#pragma unroll
            for (int c = 0; c < 4; c++)
                acc[r][c] = fmaf(a[r], b[c], acc[r][c]);
    }

    float* Sb = S + (size_t)z * SEQ * SEQ;
#pragma unroll
    for (int r = 0; r < 4; r++) {
        float4 o = make_float4(acc[r][0] * 0.125f, acc[r][1] * 0.125f,
                               acc[r][2] * 0.125f, acc[r][3] * 0.125f);
        *(float4*)(Sb + (size_t)(i0 + iy * 4 + r) * SEQ + j0 + ix * 4) = o;
    }
}

// ---------------- row softmax in place (row length 2048) -------------------
__global__ void softmax_kernel(float* __restrict__ S) {
    __shared__ float red[8];
    size_t row = blockIdx.x;
    float* p = S + row * SEQ;
    int tid = threadIdx.x;    // 256

    float4 u0 = *(float4*)(p + tid * 8);
    float4 u1 = *(float4*)(p + tid * 8 + 4);
    float v[8] = {u0.x, u0.y, u0.z, u0.w, u1.x, u1.y, u1.z, u1.w};

    float m = v[0];
#pragma unroll
    for (int i = 1; i < 8; i++) m = fmaxf(m, v[i]);
#pragma unroll
    for (int o = 16; o; o >>= 1) m = fmaxf(m, __shfl_xor_sync(0xffffffffu, m, o));
    if ((tid & 31) == 0) red[tid >> 5] = m;
    __syncthreads();
    if (tid < 32) {
        float t = red[tid & 7];
#pragma unroll
        for (int o = 4; o; o >>= 1) t = fmaxf(t, __shfl_xor_sync(0xffffffffu, t, o));
        if (tid == 0) red[0] = t;
    }
    __syncthreads();
    m = red[0];
    __syncthreads();

    float s = 0.f;
#pragma unroll
    for (int i = 0; i < 8; i++) { v[i] = expf(v[i] - m); s += v[i]; }
#pragma unroll
    for (int o = 16; o; o >>= 1) s += __shfl_xor_sync(0xffffffffu, s, o);
    if ((tid & 31) == 0) red[tid >> 5] = s;
    __syncthreads();
    if (tid < 32) {
        float t = red[tid & 7];
#pragma unroll
        for (int o = 4; o; o >>= 1) t += __shfl_xor_sync(0xffffffffu, t, o);
        if (tid == 0) red[0] = t;
    }
    __syncthreads();
    float inv = 1.f / red[0];

#pragma unroll
    for (int i = 0; i < 8; i++) v[i] *= inv;
    *(float4*)(p + tid * 8)     = make_float4(v[0], v[1], v[2], v[3]);
    *(float4*)(p + tid * 8 + 4) = make_float4(v[4], v[5], v[6], v[7]);
}

// ---------------- O = P @ V, per (b,h), written [b,n,h*64+d] ----------------
__global__ void pv_kernel(const float* __restrict__ S) {
    __shared__ float Ps[64][33];
    __shared__ float Vs[32][65];
    int tid = threadIdx.x;
    int z  = blockIdx.y;
    int i0 = blockIdx.x * 64;
    const float* Sb = S + (size_t)z * SEQ * SEQ;
    const float* Vb = g_V + (size_t)z * SEQ * DH;
    int ix = tid & 15, iy = tid >> 4;
    float acc[4][4] = {};

    for (int j0 = 0; j0 < SEQ; j0 += 32) {
#pragma unroll
        for (int t = 0; t < 2; t++) {
            int f = tid + t * 256;
            int r = f >> 3;          // 0..63
            int c = (f & 7) * 4;     // 0..28
            float4 pa = *(const float4*)(Sb + (size_t)(i0 + r) * SEQ + j0 + c);
            Ps[r][c] = pa.x; Ps[r][c+1] = pa.y; Ps[r][c+2] = pa.z; Ps[r][c+3] = pa.w;
        }
#pragma unroll
        for (int t = 0; t < 2; t++) {
            int f = tid + t * 256;
            int r = f >> 4;          // 0..31
            int c = (f & 15) * 4;
            float4 va = *(const float4*)(Vb + (size_t)(j0 + r) * DH + c);
            Vs[r][c] = va.x; Vs[r][c+1] = va.y; Vs[r][c+2] = va.z; Vs[r][c+3] = va.w;
        }
        __syncthreads();
#pragma unroll 8
        for (int jj = 0; jj < 32; jj++) {
            float a[4], b[4];
#pragma unroll
            for (int r = 0; r < 4; r++) a[r] = Ps[iy * 4 + r][jj];
#pragma unroll
            for (int c = 0; c < 4; c++) b[c] = Vs[jj][ix * 4 + c];
#pragma unroll
            for (int r = 0; r < 4; r++)
#pragma unroll
                for (int c = 0; c < 4; c++)
                    acc[r][c] = fmaf(a[r], b[c], acc[r][c]);
        }
        __syncthreads();
    }

    int bidx = z >> 4, h = z & 15;
#pragma unroll
    for (int r = 0; r < 4; r++) {
        size_t m = (size_t)bidx * SEQ + i0 + iy * 4 + r;
        *(float4*)&g_O[m * DIMD + h * 64 + ix * 4] =
            make_float4(acc[r][0], acc[r][1], acc[r][2], acc[r][3]);
    }
}

// ---------------------------- launcher -------------------------------------
extern "C" void kernel_launch(void* const* d_in, const int* in_sizes, int n_in,
                              void* d_out, int out_size) {
    const float* x    = (const float*)d_in[0];
    const float* rope = (const float*)d_in[1];
    const float* Wq   = (const float*)d_in[2];
    const float* Wk   = (const float*)d_in[3];
    const float* Wv   = (const float*)d_in[4];
    const float* Wo   = (const float*)d_in[5];
    const float* bo   = (const float*)d_in[6];

    float* out  = (float*)d_out;
    float* attn = out + OUT_ELEMS;   // second output region

    float *Qp, *Kp, *Vp;
    cudaGetSymbolAddress((void**)&Qp, g_Q);
    cudaGetSymbolAddress((void**)&Kp, g_K);
    cudaGetSymbolAddress((void**)&Vp, g_V);

    // projections into head-major scratch
    proj_gemm<<<dim3(8, 64), 256>>>(x, Wq, Qp);
    proj_gemm<<<dim3(8, 64), 256>>>(x, Wk, Kp);
    proj_gemm<<<dim3(8, 64), 256>>>(x, Wv, Vp);

    // partial rope on q, k, v
    rope_kernel<<<(BH * SEQ * 16) / 256, 256>>>(rope);

    // dots -> attn region of d_out
    qk_kernel<<<dim3(32, 32, 64), 256>>>(attn);

    // softmax in place
    softmax_kernel<<<BH * SEQ, 256>>>(attn);

    // O = attn @ V into g_O ([b,n,dim] layout)
    pv_kernel<<<dim3(32, 64), 256>>>(attn);

    // out = g_O @ Wo + bo + x
    final_gemm<<<dim3(8, 64), 256>>>(Wo, bo, x, out);
}

// round 2
// speedup vs baseline: 2.2257x; 2.2257x over previous
#include <cuda_runtime.h>
#include <math.h>

#define BB     4
#define SEQ    2048
#define DIMD   1024
#define HEADS  16
#define DH     64
#define ROT    32
#define BH     (BB*HEADS)          // 64
#define MROWS  (BB*SEQ)            // 8192
#define OUT_ELEMS ((size_t)MROWS*DIMD)

// ---------------- scratch ----------------
__device__ float g_Q[(size_t)BH*SEQ*DH];
__device__ float g_K[(size_t)BH*SEQ*DH];
__device__ float g_V[(size_t)BH*SEQ*DH];
__device__ float g_O[(size_t)MROWS*DIMD];

// ---------------- tf32 helpers ----------------
__device__ __forceinline__ unsigned f2tf(float f) {
    unsigned u;
    asm("cvt.rna.tf32.f32 %0, %1;" : "=r"(u) : "f"(f));
    return u;
}

__device__ __forceinline__ void mma_tf32(float d[4], const unsigned a[4],
                                         const unsigned b[2], const float c[4]) {
    asm volatile(
        "mma.sync.aligned.m16n8k8.row.col.f32.tf32.tf32.f32 "
        "{%0,%1,%2,%3}, {%4,%5,%6,%7}, {%8,%9}, {%10,%11,%12,%13};"
        : "=f"(d[0]), "=f"(d[1]), "=f"(d[2]), "=f"(d[3])
        : "r"(a[0]), "r"(a[1]), "r"(a[2]), "r"(a[3]),
          "r"(b[0]), "r"(b[1]),
          "f"(c[0]), "f"(c[1]), "f"(c[2]), "f"(c[3]));
}

// ============ 128x128x16 tf32 block GEMM core (proj / final) ==============
// A: X [8192,1024] rm,  B: W [1024,1024] rm.  8 warps: 2(m) x 4(n), warp 64x32.
// mode 0: write head-major permuted. mode 1: add bias+resid, write row-major.
template <int MODE>
__global__ __launch_bounds__(256) void gemm1024_tf32(
    const float* __restrict__ X, const float* __restrict__ W,
    const float* __restrict__ bo, const float* __restrict__ resid,
    float* __restrict__ Y)
{
    __shared__ unsigned As[128][20];   // [m][k], pad 4
    __shared__ unsigned Bs[16][132];   // [k][n], pad 4
    int t = threadIdx.x;
    int w = t >> 5, lane = t & 31, g = lane >> 2, tq = lane & 3;
    int wm = w & 1, wn = w >> 1;
    int row0 = blockIdx.y * 128, col0 = blockIdx.x * 128;

    float acc[4][4][4];
#pragma unroll
    for (int i = 0; i < 4; i++)
#pragma unroll
        for (int j = 0; j < 4; j++)
#pragma unroll
            for (int r = 0; r < 4; r++) acc[i][j][r] = 0.f;

    for (int k0 = 0; k0 < DIMD; k0 += 16) {
#pragma unroll
        for (int it = 0; it < 2; it++) {
            int v = t + it * 256;
            int m = v >> 2, kv = (v & 3) << 2;
            float4 x4 = *(const float4*)(X + (size_t)(row0 + m) * DIMD + k0 + kv);
            *(uint4*)&As[m][kv] = make_uint4(f2tf(x4.x), f2tf(x4.y), f2tf(x4.z), f2tf(x4.w));
            int kk = v >> 5, nv = (v & 31) << 2;
            float4 w4 = *(const float4*)(W + (size_t)(k0 + kk) * DIMD + col0 + nv);
            *(uint4*)&Bs[kk][nv] = make_uint4(f2tf(w4.x), f2tf(w4.y), f2tf(w4.z), f2tf(w4.w));
        }
        __syncthreads();
#pragma unroll
        for (int ks = 0; ks < 2; ks++) {
            int kb = ks * 8;
            unsigned a[4][4], b[4][2];
#pragma unroll
            for (int mt = 0; mt < 4; mt++) {
                int mr = wm * 64 + mt * 16 + g;
                a[mt][0] = As[mr][kb + tq];
                a[mt][1] = As[mr + 8][kb + tq];
                a[mt][2] = As[mr][kb + tq + 4];
                a[mt][3] = As[mr + 8][kb + tq + 4];
            }
#pragma unroll
            for (int nt = 0; nt < 4; nt++) {
                int nc = wn * 32 + nt * 8 + g;
                b[nt][0] = Bs[kb + tq][nc];
                b[nt][1] = Bs[kb + tq + 4][nc];
            }
#pragma unroll
            for (int mt = 0; mt < 4; mt++)
#pragma unroll
                for (int nt = 0; nt < 4; nt++)
                    mma_tf32(acc[mt][nt], a[mt], b[nt], acc[mt][nt]);
        }
        __syncthreads();
    }

#pragma unroll
    for (int mt = 0; mt < 4; mt++) {
#pragma unroll
        for (int nt = 0; nt < 4; nt++) {
            int c = col0 + wn * 32 + nt * 8 + 2 * tq;
#pragma unroll
            for (int half = 0; half < 2; half++) {
                int m = row0 + wm * 64 + mt * 16 + g + half * 8;
                float2 val = make_float2(acc[mt][nt][half * 2], acc[mt][nt][half * 2 + 1]);
                if (MODE == 0) {
                    int bi = m >> 11, n = m & 2047, h = c >> 6, d = c & 63;
                    *(float2*)&Y[(((size_t)(bi * HEADS + h) * SEQ + n) << 6) + d] = val;
                } else {
                    float2 bv = *(const float2*)&bo[c];
                    float2 rv = *(const float2*)&resid[(size_t)m * DIMD + c];
                    val.x += bv.x + rv.x;
                    val.y += bv.y + rv.y;
                    *(float2*)&Y[(size_t)m * DIMD + c] = val;
                }
            }
        }
    }
}

// ---------------- partial RoPE on first 32 dims of q,k,v -------------------
__global__ void rope_kernel(const float* __restrict__ rope) {
    int idx = blockIdx.x * blockDim.x + threadIdx.x;
    if (idx >= BH * SEQ * 16) return;
    int p = idx & 15;
    int n = (idx >> 4) & (SEQ - 1);
    int z = idx >> 15;
    size_t base = ((size_t)z * SEQ + n) * DH;
    float r1 = rope[n * ROT + p];
    float r2 = rope[n * ROT + p + 16];
    float c1 = cosf(r1), s1 = sinf(r1);
    float c2 = cosf(r2), s2 = sinf(r2);
    float* arrs[3] = {g_Q, g_K, g_V};
#pragma unroll
    for (int a = 0; a < 3; a++) {
        float t0 = arrs[a][base + p];
        float t1 = arrs[a][base + p + 16];
        arrs[a][base + p]      = t0 * c1 - t1 * s1;
        arrs[a][base + p + 16] = t1 * c2 + t0 * s2;
    }
}

// ============ S = scale * Q @ K^T (tf32 MMA), per (b,h) ==============
// Block 128x128, K=64 in two 32-chunks. 8 warps 2x4.
__global__ __launch_bounds__(256) void qk_tf32(float* __restrict__ S) {
    __shared__ unsigned Qs[128][36];
    __shared__ unsigned Ks[128][36];
    int t = threadIdx.x;
    int w = t >> 5, lane = t & 31, g = lane >> 2, tq = lane & 3;
    int wm = w & 1, wn = w >> 1;
    int z = blockIdx.z;
    int i0 = blockIdx.y * 128, j0 = blockIdx.x * 128;
    const float* Qb = g_Q + (size_t)z * SEQ * DH;
    const float* Kb = g_K + (size_t)z * SEQ * DH;

    float acc[4][4][4];
#pragma unroll
    for (int i = 0; i < 4; i++)
#pragma unroll
        for (int j = 0; j < 4; j++)
#pragma unroll
            for (int r = 0; r < 4; r++) acc[i][j][r] = 0.f;

    for (int kc = 0; kc < DH; kc += 32) {
#pragma unroll
        for (int it = 0; it < 4; it++) {
            int v = t + it * 256;
            int m = v >> 3, kv = (v & 7) << 2;
            float4 q4 = *(const float4*)(Qb + (size_t)(i0 + m) * DH + kc + kv);
            *(uint4*)&Qs[m][kv] = make_uint4(f2tf(q4.x), f2tf(q4.y), f2tf(q4.z), f2tf(q4.w));
            float4 k4 = *(const float4*)(Kb + (size_t)(j0 + m) * DH + kc + kv);
            *(uint4*)&Ks[m][kv] = make_uint4(f2tf(k4.x), f2tf(k4.y), f2tf(k4.z), f2tf(k4.w));
        }
        __syncthreads();
#pragma unroll
        for (int ks = 0; ks < 4; ks++) {
            int kb = ks * 8;
            unsigned a[4][4], b[4][2];
#pragma unroll
            for (int mt = 0; mt < 4; mt++) {
                int mr = wm * 64 + mt * 16 + g;
                a[mt][0] = Qs[mr][kb + tq];
                a[mt][1] = Qs[mr + 8][kb + tq];
                a[mt][2] = Qs[mr][kb + tq + 4];
                a[mt][3] = Qs[mr + 8][kb + tq + 4];
            }
#pragma unroll
            for (int nt = 0; nt < 4; nt++) {
                int nr = wn * 32 + nt * 8 + g;
                b[nt][0] = Ks[nr][kb + tq];
                b[nt][1] = Ks[nr][kb + tq + 4];
            }
#pragma unroll
            for (int mt = 0; mt < 4; mt++)
#pragma unroll
                for (int nt = 0; nt < 4; nt++)
                    mma_tf32(acc[mt][nt], a[mt], b[nt], acc[mt][nt]);
        }
        __syncthreads();
    }

    float* Sb = S + (size_t)z * SEQ * SEQ;
#pragma unroll
    for (int mt = 0; mt < 4; mt++) {
#pragma unroll
        for (int nt = 0; nt < 4; nt++) {
            int c = j0 + wn * 32 + nt * 8 + 2 * tq;
#pragma unroll
            for (int half = 0; half < 2; half++) {
                int m = i0 + wm * 64 + mt * 16 + g + half * 8;
                float2 val = make_float2(acc[mt][nt][half * 2] * 0.125f,
                                         acc[mt][nt][half * 2 + 1] * 0.125f);
                *(float2*)&Sb[(size_t)m * SEQ + c] = val;
            }
        }
    }
}

// ---------------- row softmax in place ----------------
__global__ void softmax_kernel(float* __restrict__ S) {
    __shared__ float red[8];
    size_t row = blockIdx.x;
    float* p = S + row * SEQ;
    int tid = threadIdx.x;

    float4 u0 = *(float4*)(p + tid * 8);
    float4 u1 = *(float4*)(p + tid * 8 + 4);
    float v[8] = {u0.x, u0.y, u0.z, u0.w, u1.x, u1.y, u1.z, u1.w};

    float m = v[0];
#pragma unroll
    for (int i = 1; i < 8; i++) m = fmaxf(m, v[i]);
#pragma unroll
    for (int o = 16; o; o >>= 1) m = fmaxf(m, __shfl_xor_sync(0xffffffffu, m, o));
    if ((tid & 31) == 0) red[tid >> 5] = m;
    __syncthreads();
    if (tid < 32) {
        float tt = red[tid & 7];
#pragma unroll
        for (int o = 4; o; o >>= 1) tt = fmaxf(tt, __shfl_xor_sync(0xffffffffu, tt, o));
        if (tid == 0) red[0] = tt;
    }
    __syncthreads();
    m = red[0];
    __syncthreads();

    float s = 0.f;
#pragma unroll
    for (int i = 0; i < 8; i++) { v[i] = expf(v[i] - m); s += v[i]; }
#pragma unroll
    for (int o = 16; o; o >>= 1) s += __shfl_xor_sync(0xffffffffu, s, o);
    if ((tid & 31) == 0) red[tid >> 5] = s;
    __syncthreads();
    if (tid < 32) {
        float tt = red[tid & 7];
#pragma unroll
        for (int o = 4; o; o >>= 1) tt += __shfl_xor_sync(0xffffffffu, tt, o);
        if (tid == 0) red[0] = tt;
    }
    __syncthreads();
    float inv = 1.f / red[0];

#pragma unroll
    for (int i = 0; i < 8; i++) v[i] *= inv;
    *(float4*)(p + tid * 8)     = make_float4(v[0], v[1], v[2], v[3]);
    *(float4*)(p + tid * 8 + 4) = make_float4(v[4], v[5], v[6], v[7]);
}

// ============ O = P @ V (tf32 MMA), per (b,h), write [b,n,h*64+d] ==========
// Block 128x64, K-loop 32. 8 warps 2x4, warp tile 64x16.
__global__ __launch_bounds__(256) void pv_tf32(const float* __restrict__ S) {
    __shared__ unsigned Ps[128][36];   // [m][k]
    __shared__ unsigned Vs[32][68];    // [k][n]
    int t = threadIdx.x;
    int w = t >> 5, lane = t & 31, g = lane >> 2, tq = lane & 3;
    int wm = w & 1, wn = w >> 1;
    int z = blockIdx.y;
    int i0 = blockIdx.x * 128;
    const float* Sb = S + (size_t)z * SEQ * SEQ;
    const float* Vb = g_V + (size_t)z * SEQ * DH;

    float acc[4][2][4];
#pragma unroll
    for (int i = 0; i < 4; i++)
#pragma unroll
        for (int j = 0; j < 2; j++)
#pragma unroll
            for (int r = 0; r < 4; r++) acc[i][j][r] = 0.f;

    for (int j0 = 0; j0 < SEQ; j0 += 32) {
#pragma unroll
        for (int it = 0; it < 4; it++) {
            int v = t + it * 256;
            int m = v >> 3, kv = (v & 7) << 2;
            float4 p4 = *(const float4*)(Sb + (size_t)(i0 + m) * SEQ + j0 + kv);
            *(uint4*)&Ps[m][kv] = make_uint4(f2tf(p4.x), f2tf(p4.y), f2tf(p4.z), f2tf(p4.w));
        }
#pragma unroll
        for (int it = 0; it < 2; it++) {
            int v = t + it * 256;
            int kk = v >> 4, nv = (v & 15) << 2;
            float4 v4 = *(const float4*)(Vb + (size_t)(j0 + kk) * DH + nv);
            *(uint4*)&Vs[kk][nv] = make_uint4(f2tf(v4.x), f2tf(v4.y), f2tf(v4.z), f2tf(v4.w));
        }
        __syncthreads();
#pragma unroll
        for (int ks = 0; ks < 4; ks++) {
            int kb = ks * 8;
            unsigned a[4][4], b[2][2];
#pragma unroll
            for (int mt = 0; mt < 4; mt++) {
                int mr = wm * 64 + mt * 16 + g;
                a[mt][0] = Ps[mr][kb + tq];
                a[mt][1] = Ps[mr + 8][kb + tq];
                a[mt][2] = Ps[mr][kb + tq + 4];
                a[mt][3] = Ps[mr + 8][kb + tq + 4];
            }
#pragma unroll
            for (int nt = 0; nt < 2; nt++) {
                int nc = wn * 16 + nt * 8 + g;
                b[nt][0] = Vs[kb + tq][nc];
                b[nt][1] = Vs[kb + tq + 4][nc];
            }
#pragma unroll
            for (int mt = 0; mt < 4; mt++)
#pragma unroll
                for (int nt = 0; nt < 2; nt++)
                    mma_tf32(acc[mt][nt], a[mt], b[nt], acc[mt][nt]);
        }
        __syncthreads();
    }

    int bi = z >> 4, h = z & 15;
#pragma unroll
    for (int mt = 0; mt < 4; mt++) {
#pragma unroll
        for (int nt = 0; nt < 2; nt++) {
            int c = wn * 16 + nt * 8 + 2 * tq;
#pragma unroll
            for (int half = 0; half < 2; half++) {
                int m = i0 + wm * 64 + mt * 16 + g + half * 8;
                float2 val = make_float2(acc[mt][nt][half * 2], acc[mt][nt][half * 2 + 1]);
                *(float2*)&g_O[((size_t)bi * SEQ + m) * DIMD + h * 64 + c] = val;
            }
        }
    }
}

// ---------------------------- launcher -------------------------------------
extern "C" void kernel_launch(void* const* d_in, const int* in_sizes, int n_in,
                              void* d_out, int out_size) {
    const float* x    = (const float*)d_in[0];
    const float* rope = (const float*)d_in[1];
    const float* Wq   = (const float*)d_in[2];
    const float* Wk   = (const float*)d_in[3];
    const float* Wv   = (const float*)d_in[4];
    const float* Wo   = (const float*)d_in[5];
    const float* bo   = (const float*)d_in[6];

    float* out  = (float*)d_out;
    float* attn = out + OUT_ELEMS;

    float *Qp, *Kp, *Vp, *Op;
    cudaGetSymbolAddress((void**)&Qp, g_Q);
    cudaGetSymbolAddress((void**)&Kp, g_K);
    cudaGetSymbolAddress((void**)&Vp, g_V);
    cudaGetSymbolAddress((void**)&Op, g_O);

    gemm1024_tf32<0><<<dim3(8, 64), 256>>>(x, Wq, nullptr, nullptr, Qp);
    gemm1024_tf32<0><<<dim3(8, 64), 256>>>(x, Wk, nullptr, nullptr, Kp);
    gemm1024_tf32<0><<<dim3(8, 64), 256>>>(x, Wv, nullptr, nullptr, Vp);

    rope_kernel<<<(BH * SEQ * 16) / 256, 256>>>(rope);

    qk_tf32<<<dim3(16, 16, 64), 256>>>(attn);

    softmax_kernel<<<BH * SEQ, 256>>>(attn);

    pv_tf32<<<dim3(16, 64), 256>>>(attn);

    gemm1024_tf32<1><<<dim3(8, 64), 256>>>(Op, Wo, bo, x, out);
}

// round 3
// speedup vs baseline: 2.3347x; 1.0490x over previous
#include <cuda_runtime.h>
#include <math.h>

#define BB     4
#define SEQ    2048
#define DIMD   1024
#define HEADS  16
#define DH     64
#define ROT    32
#define BH     (BB*HEADS)          // 64
#define MROWS  (BB*SEQ)            // 8192
#define NROWS  ((size_t)BH*SEQ)    // 131072
#define OUT_ELEMS ((size_t)MROWS*DIMD)

// ---------------- scratch ----------------
__device__ float g_Q[(size_t)BH*SEQ*DH];
__device__ float g_K[(size_t)BH*SEQ*DH];
__device__ float g_V[(size_t)BH*SEQ*DH];
__device__ float g_O[(size_t)MROWS*DIMD];
__device__ float g_part[16 * NROWS];   // per-j-block partial row sums
__device__ float g_inv[NROWS];         // 1/rowsum

// ---------------- tf32 helpers ----------------
__device__ __forceinline__ unsigned f2tf(float f) {
    unsigned u;
    asm("cvt.rna.tf32.f32 %0, %1;" : "=r"(u) : "f"(f));
    return u;
}

__device__ __forceinline__ void mma_tf32(float d[4], const unsigned a[4],
                                         const unsigned b[2], const float c[4]) {
    asm volatile(
        "mma.sync.aligned.m16n8k8.row.col.f32.tf32.tf32.f32 "
        "{%0,%1,%2,%3}, {%4,%5,%6,%7}, {%8,%9}, {%10,%11,%12,%13};"
        : "=f"(d[0]), "=f"(d[1]), "=f"(d[2]), "=f"(d[3])
        : "r"(a[0]), "r"(a[1]), "r"(a[2]), "r"(a[3]),
          "r"(b[0]), "r"(b[1]),
          "f"(c[0]), "f"(c[1]), "f"(c[2]), "f"(c[3]));
}

// ============ 128x128x16 tf32 block GEMM (proj / final), reg double-buffer ==
template <int MODE>
__global__ __launch_bounds__(256) void gemm1024_tf32(
    const float* __restrict__ X, const float* __restrict__ W,
    const float* __restrict__ bo, const float* __restrict__ resid,
    float* __restrict__ Y)
{
    __shared__ unsigned As[128][20];   // [m][k], pad 4
    __shared__ unsigned Bs[16][132];   // [k][n], pad 4
    int t = threadIdx.x;
    int w = t >> 5, lane = t & 31, g = lane >> 2, tq = lane & 3;
    int wm = w & 1, wn = w >> 1;
    int row0 = blockIdx.y * 128, col0 = blockIdx.x * 128;

    float acc[4][4][4];
#pragma unroll
    for (int i = 0; i < 4; i++)
#pragma unroll
        for (int j = 0; j < 4; j++)
#pragma unroll
            for (int r = 0; r < 4; r++) acc[i][j][r] = 0.f;

    // per-it addressing
    int amr[2], akv[2], bkk[2], bnv[2];
#pragma unroll
    for (int it = 0; it < 2; it++) {
        int v = t + it * 256;
        amr[it] = v >> 2;  akv[it] = (v & 3) << 2;
        bkk[it] = v >> 5;  bnv[it] = (v & 31) << 2;
    }

    float4 xa[2], wb[2];
#pragma unroll
    for (int it = 0; it < 2; it++) {
        xa[it] = *(const float4*)(X + (size_t)(row0 + amr[it]) * DIMD + akv[it]);
        wb[it] = *(const float4*)(W + (size_t)(bkk[it]) * DIMD + col0 + bnv[it]);
    }

    for (int k0 = 0; k0 < DIMD; k0 += 16) {
#pragma unroll
        for (int it = 0; it < 2; it++) {
            *(uint4*)&As[amr[it]][akv[it]] =
                make_uint4(f2tf(xa[it].x), f2tf(xa[it].y), f2tf(xa[it].z), f2tf(xa[it].w));
            *(uint4*)&Bs[bkk[it]][bnv[it]] =
                make_uint4(f2tf(wb[it].x), f2tf(wb[it].y), f2tf(wb[it].z), f2tf(wb[it].w));
        }
        __syncthreads();
        if (k0 + 16 < DIMD) {
#pragma unroll
            for (int it = 0; it < 2; it++) {
                xa[it] = *(const float4*)(X + (size_t)(row0 + amr[it]) * DIMD + k0 + 16 + akv[it]);
                wb[it] = *(const float4*)(W + (size_t)(k0 + 16 + bkk[it]) * DIMD + col0 + bnv[it]);
            }
        }
#pragma unroll
        for (int ks = 0; ks < 2; ks++) {
            int kb = ks * 8;
            unsigned a[4][4], b[4][2];
#pragma unroll
            for (int mt = 0; mt < 4; mt++) {
                int mr = wm * 64 + mt * 16 + g;
                a[mt][0] = As[mr][kb + tq];
                a[mt][1] = As[mr + 8][kb + tq];
                a[mt][2] = As[mr][kb + tq + 4];
                a[mt][3] = As[mr + 8][kb + tq + 4];
            }
#pragma unroll
            for (int nt = 0; nt < 4; nt++) {
                int nc = wn * 32 + nt * 8 + g;
                b[nt][0] = Bs[kb + tq][nc];
                b[nt][1] = Bs[kb + tq + 4][nc];
            }
#pragma unroll
            for (int mt = 0; mt < 4; mt++)
#pragma unroll
                for (int nt = 0; nt < 4; nt++)
                    mma_tf32(acc[mt][nt], a[mt], b[nt], acc[mt][nt]);
        }
        __syncthreads();
    }

#pragma unroll
    for (int mt = 0; mt < 4; mt++) {
#pragma unroll
        for (int nt = 0; nt < 4; nt++) {
            int c = col0 + wn * 32 + nt * 8 + 2 * tq;
#pragma unroll
            for (int half = 0; half < 2; half++) {
                int m = row0 + wm * 64 + mt * 16 + g + half * 8;
                float2 val = make_float2(acc[mt][nt][half * 2], acc[mt][nt][half * 2 + 1]);
                if (MODE == 0) {
                    int bi = m >> 11, n = m & 2047, h = c >> 6, d = c & 63;
                    *(float2*)&Y[(((size_t)(bi * HEADS + h) * SEQ + n) << 6) + d] = val;
                } else {
                    float2 bv = *(const float2*)&bo[c];
                    float2 rv = *(const float2*)&resid[(size_t)m * DIMD + c];
                    val.x += bv.x + rv.x;
                    val.y += bv.y + rv.y;
                    *(float2*)&Y[(size_t)m * DIMD + c] = val;
                }
            }
        }
    }
}

// ---------------- partial RoPE on first 32 dims of q,k,v -------------------
__global__ void rope_kernel(const float* __restrict__ rope) {
    int idx = blockIdx.x * blockDim.x + threadIdx.x;
    if (idx >= BH * SEQ * 16) return;
    int p = idx & 15;
    int n = (idx >> 4) & (SEQ - 1);
    int z = idx >> 15;
    size_t base = ((size_t)z * SEQ + n) * DH;
    float r1 = rope[n * ROT + p];
    float r2 = rope[n * ROT + p + 16];
    float c1 = cosf(r1), s1 = sinf(r1);
    float c2 = cosf(r2), s2 = sinf(r2);
    float* arrs[3] = {g_Q, g_K, g_V};
#pragma unroll
    for (int a = 0; a < 3; a++) {
        float t0 = arrs[a][base + p];
        float t1 = arrs[a][base + p + 16];
        arrs[a][base + p]      = t0 * c1 - t1 * s1;
        arrs[a][base + p + 16] = t1 * c2 + t0 * s2;
    }
}

// ============ P_unnorm = exp(scale * Q K^T); partial row sums =============
// Block 128x128. 8 warps 2(m)x4(n). Dynamic smem.
__global__ __launch_bounds__(256) void qk_exp(float* __restrict__ S) {
    extern __shared__ char smem_raw[];
    unsigned (*Qs)[68] = (unsigned (*)[68])smem_raw;                 // 128x68
    unsigned (*Ks)[68] = (unsigned (*)[68])(smem_raw + 128*68*4);    // 128x68
    float (*part)[4]   = (float (*)[4])(smem_raw + 2*128*68*4);     // 128x4

    int t = threadIdx.x;
    int w = t >> 5, lane = t & 31, g = lane >> 2, tq = lane & 3;
    int wm = w & 1, wn = w >> 1;
    int z = blockIdx.z;
    int i0 = blockIdx.y * 128, j0 = blockIdx.x * 128;
    const float* Qb = g_Q + (size_t)z * SEQ * DH;
    const float* Kb = g_K + (size_t)z * SEQ * DH;

    // load 128x64 Q and K tiles (8 float4 per thread each)
#pragma unroll
    for (int it = 0; it < 8; it++) {
        int v = t + it * 256;
        int m = v >> 4, kv = (v & 15) << 2;
        float4 q4 = *(const float4*)(Qb + (size_t)(i0 + m) * DH + kv);
        *(uint4*)&Qs[m][kv] = make_uint4(f2tf(q4.x), f2tf(q4.y), f2tf(q4.z), f2tf(q4.w));
        float4 k4 = *(const float4*)(Kb + (size_t)(j0 + m) * DH + kv);
        *(uint4*)&Ks[m][kv] = make_uint4(f2tf(k4.x), f2tf(k4.y), f2tf(k4.z), f2tf(k4.w));
    }
    __syncthreads();

    float acc[4][4][4];
#pragma unroll
    for (int i = 0; i < 4; i++)
#pragma unroll
        for (int j = 0; j < 4; j++)
#pragma unroll
            for (int r = 0; r < 4; r++) acc[i][j][r] = 0.f;

#pragma unroll
    for (int ks = 0; ks < 8; ks++) {
        int kb = ks * 8;
        unsigned a[4][4], b[4][2];
#pragma unroll
        for (int mt = 0; mt < 4; mt++) {
            int mr = wm * 64 + mt * 16 + g;
            a[mt][0] = Qs[mr][kb + tq];
            a[mt][1] = Qs[mr + 8][kb + tq];
            a[mt][2] = Qs[mr][kb + tq + 4];
            a[mt][3] = Qs[mr + 8][kb + tq + 4];
        }
#pragma unroll
        for (int nt = 0; nt < 4; nt++) {
            int nr = wn * 32 + nt * 8 + g;
            b[nt][0] = Ks[nr][kb + tq];
            b[nt][1] = Ks[nr][kb + tq + 4];
        }
#pragma unroll
        for (int mt = 0; mt < 4; mt++)
#pragma unroll
            for (int nt = 0; nt < 4; nt++)
                mma_tf32(acc[mt][nt], a[mt], b[nt], acc[mt][nt]);
    }

    // exp + write unnormalized + partial row sums
    float* Sb = S + (size_t)z * SEQ * SEQ;
#pragma unroll
    for (int mt = 0; mt < 4; mt++) {
#pragma unroll
        for (int half = 0; half < 2; half++) {
            float rpart = 0.f;
#pragma unroll
            for (int nt = 0; nt < 4; nt++) {
                float p0 = __expf(acc[mt][nt][half * 2]     * 0.125f);
                float p1 = __expf(acc[mt][nt][half * 2 + 1] * 0.125f);
                rpart += p0 + p1;
                int c = j0 + wn * 32 + nt * 8 + 2 * tq;
                int m = i0 + wm * 64 + mt * 16 + g + half * 8;
                *(float2*)&Sb[(size_t)m * SEQ + c] = make_float2(p0, p1);
            }
            // reduce over tq (lanes xor 1, 2)
            rpart += __shfl_xor_sync(0xffffffffu, rpart, 1);
            rpart += __shfl_xor_sync(0xffffffffu, rpart, 2);
            if (tq == 0) {
                int row = wm * 64 + mt * 16 + half * 8 + g;
                part[row][wn] = rpart;
            }
        }
    }
    __syncthreads();
    if (t < 128) {
        float s = part[t][0] + part[t][1] + part[t][2] + part[t][3];
        g_part[(size_t)blockIdx.x * NROWS + (size_t)z * SEQ + i0 + t] = s;
    }
}

// ---------------- inv = 1 / sum(partials) ----------------
__global__ void reduce_inv() {
    size_t i = (size_t)blockIdx.x * blockDim.x + threadIdx.x;
    if (i >= NROWS) return;
    float s = 0.f;
#pragma unroll
    for (int j = 0; j < 16; j++) s += g_part[(size_t)j * NROWS + i];
    g_inv[i] = 1.f / s;
}

// ============ normalize attn in place + O = P @ V ==========================
// Block: 128 rows x all K. 8 warps 2(m)x4(n). Dynamic smem.
__global__ __launch_bounds__(256) void pv_norm(float* __restrict__ S) {
    extern __shared__ char smem_raw[];
    unsigned (*Ps)[132] = (unsigned (*)[132])smem_raw;                  // 128x132
    unsigned (*Vs)[68]  = (unsigned (*)[68])(smem_raw + 128*132*4);     // 128x68
    float* inv_s        = (float*)(smem_raw + 128*132*4 + 128*68*4);    // 128

    int t = threadIdx.x;
    int w = t >> 5, lane = t & 31, g = lane >> 2, tq = lane & 3;
    int wm = w & 1, wn = w >> 1;
    int z = blockIdx.y;
    int i0 = blockIdx.x * 128;
    float* Sb = S + (size_t)z * SEQ * SEQ;
    const float* Vb = g_V + (size_t)z * SEQ * DH;

    if (t < 128) inv_s[t] = g_inv[(size_t)z * SEQ + i0 + t];

    float acc[4][2][4];
#pragma unroll
    for (int i = 0; i < 4; i++)
#pragma unroll
        for (int j = 0; j < 2; j++)
#pragma unroll
            for (int r = 0; r < 4; r++) acc[i][j][r] = 0.f;

    for (int j0 = 0; j0 < SEQ; j0 += 128) {
        __syncthreads();   // protect Ps/Vs from previous iteration's reads
        // load P tile, normalize in place, stage tf32
#pragma unroll
        for (int it = 0; it < 16; it++) {
            int v = t + it * 256;
            int m = v >> 5, c4 = (v & 31) << 2;
            float* gp = Sb + (size_t)(i0 + m) * SEQ + j0 + c4;
            float4 p4 = *(float4*)gp;
            float iv = inv_s[m];
            p4.x *= iv; p4.y *= iv; p4.z *= iv; p4.w *= iv;
            *(float4*)gp = p4;
            *(uint4*)&Ps[m][c4] = make_uint4(f2tf(p4.x), f2tf(p4.y), f2tf(p4.z), f2tf(p4.w));
        }
        // load V tile
#pragma unroll
        for (int it = 0; it < 8; it++) {
            int v = t + it * 256;
            int m = v >> 4, kv = (v & 15) << 2;
            float4 v4 = *(const float4*)(Vb + (size_t)(j0 + m) * DH + kv);
            *(uint4*)&Vs[m][kv] = make_uint4(f2tf(v4.x), f2tf(v4.y), f2tf(v4.z), f2tf(v4.w));
        }
        __syncthreads();
#pragma unroll
        for (int ks = 0; ks < 16; ks++) {
            int kb = ks * 8;
            unsigned a[4][4], b[2][2];
#pragma unroll
            for (int mt = 0; mt < 4; mt++) {
                int mr = wm * 64 + mt * 16 + g;
                a[mt][0] = Ps[mr][kb + tq];
                a[mt][1] = Ps[mr + 8][kb + tq];
                a[mt][2] = Ps[mr][kb + tq + 4];
                a[mt][3] = Ps[mr + 8][kb + tq + 4];
            }
#pragma unroll
            for (int nt = 0; nt < 2; nt++) {
                int nc = wn * 16 + nt * 8 + g;
                b[nt][0] = Vs[kb + tq][nc];
                b[nt][1] = Vs[kb + tq + 4][nc];
            }
#pragma unroll
            for (int mt = 0; mt < 4; mt++)
#pragma unroll
                for (int nt = 0; nt < 2; nt++)
                    mma_tf32(acc[mt][nt], a[mt], b[nt], acc[mt][nt]);
        }
    }

    int bi = z >> 4, h = z & 15;
#pragma unroll
    for (int mt = 0; mt < 4; mt++) {
#pragma unroll
        for (int nt = 0; nt < 2; nt++) {
            int c = wn * 16 + nt * 8 + 2 * tq;
#pragma unroll
            for (int half = 0; half < 2; half++) {
                int m = i0 + wm * 64 + mt * 16 + g + half * 8;
                float2 val = make_float2(acc[mt][nt][half * 2], acc[mt][nt][half * 2 + 1]);
                *(float2*)&g_O[((size_t)bi * SEQ + m) * DIMD + h * 64 + c] = val;
            }
        }
    }
}

// ---------------------------- launcher -------------------------------------
extern "C" void kernel_launch(void* const* d_in, const int* in_sizes, int n_in,
                              void* d_out, int out_size) {
    const float* x    = (const float*)d_in[0];
    const float* rope = (const float*)d_in[1];
    const float* Wq   = (const float*)d_in[2];
    const float* Wk   = (const float*)d_in[3];
    const float* Wv   = (const float*)d_in[4];
    const float* Wo   = (const float*)d_in[5];
    const float* bo   = (const float*)d_in[6];

    float* out  = (float*)d_out;
    float* attn = out + OUT_ELEMS;

    float *Qp, *Kp, *Vp, *Op;
    cudaGetSymbolAddress((void**)&Qp, g_Q);
    cudaGetSymbolAddress((void**)&Kp, g_K);
    cudaGetSymbolAddress((void**)&Vp, g_V);
    cudaGetSymbolAddress((void**)&Op, g_O);

    const int QK_SMEM = 2 * 128 * 68 * 4 + 128 * 4 * 4;           // 71680
    const int PV_SMEM = 128 * 132 * 4 + 128 * 68 * 4 + 128 * 4;   // 102912
    cudaFuncSetAttribute(qk_exp,  cudaFuncAttributeMaxDynamicSharedMemorySize, QK_SMEM);
    cudaFuncSetAttribute(pv_norm, cudaFuncAttributeMaxDynamicSharedMemorySize, PV_SMEM);

    gemm1024_tf32<0><<<dim3(8, 64), 256>>>(x, Wq, nullptr, nullptr, Qp);
    gemm1024_tf32<0><<<dim3(8, 64), 256>>>(x, Wk, nullptr, nullptr, Kp);
    gemm1024_tf32<0><<<dim3(8, 64), 256>>>(x, Wv, nullptr, nullptr, Vp);

    rope_kernel<<<(BH * SEQ * 16) / 256, 256>>>(rope);

    qk_exp<<<dim3(16, 16, 64), 256, QK_SMEM>>>(attn);

    reduce_inv<<<(int)(NROWS / 256), 256>>>();

    pv_norm<<<dim3(16, 64), 256, PV_SMEM>>>(attn);

    gemm1024_tf32<1><<<dim3(8, 64), 256>>>(Op, Wo, bo, x, out);
}

// round 6
// speedup vs baseline: 3.6220x; 1.5514x over previous
#include <cuda_runtime.h>
#include <cuda_fp16.h>
#include <math.h>
#include <stdint.h>

#define BB     4
#define SEQ    2048
#define DIMD   1024
#define HEADS  16
#define DH     64
#define ROT    32
#define BH     (BB*HEADS)          // 64
#define MROWS  (BB*SEQ)            // 8192
#define NROWS  ((size_t)BH*SEQ)    // 131072
#define OUT_ELEMS ((size_t)MROWS*DIMD)

// ---------------- scratch ----------------
__device__ float g_Q[(size_t)BH*SEQ*DH];
__device__ float g_K[(size_t)BH*SEQ*DH];
__device__ float g_V[(size_t)BH*SEQ*DH];
__device__ float g_O[(size_t)MROWS*DIMD];
__device__ float g_part[16 * NROWS];   // per-j-block partial row sums
__device__ float g_inv[NROWS];         // 1/rowsum

// ---------------- helpers ----------------
__device__ __forceinline__ unsigned f2h2(float a, float b) {
    unsigned u;
    asm("cvt.rn.f16x2.f32 %0, %2, %1;" : "=r"(u) : "f"(a), "f"(b));
    return u;
}

// fp16 MMA m16n8k16, f32 accumulate
__device__ __forceinline__ void mma_f16(float d[4], const unsigned a[4],
                                        const unsigned b[2], const float c[4]) {
    asm volatile(
        "mma.sync.aligned.m16n8k16.row.col.f32.f16.f16.f32 "
        "{%0,%1,%2,%3}, {%4,%5,%6,%7}, {%8,%9}, {%10,%11,%12,%13};"
        : "=f"(d[0]), "=f"(d[1]), "=f"(d[2]), "=f"(d[3])
        : "r"(a[0]), "r"(a[1]), "r"(a[2]), "r"(a[3]),
          "r"(b[0]), "r"(b[1]),
          "f"(c[0]), "f"(c[1]), "f"(c[2]), "f"(c[3]));
}

// ============ 128x128x32 fp16 block GEMM (proj / final) ====================
// A: X [8192,1024] rm,  B: W [1024,1024] rm (used as col-major fragment).
// 8 warps 2(m) x 4(n), warp tile 64x32.
// MODE 0: head-major permuted out. MODE 1: +bo+resid row-major out.
template <int MODE>
__global__ __launch_bounds__(256) void gemm1024_f16(
    const float* __restrict__ X, const float* __restrict__ W,
    const float* __restrict__ bo, const float* __restrict__ resid,
    float* __restrict__ Y)
{
    __shared__ unsigned As[128][20];   // [m][kp], 16 used, stride 20 (conflict-free)
    __shared__ unsigned Bs[16][136];   // [kp][n], stride 136 (conflict-free)
    int t = threadIdx.x;
    int w = t >> 5, lane = t & 31, g = lane >> 2, tq = lane & 3;
    int wm = w & 1, wn = w >> 1;
    int row0 = blockIdx.y * 128, col0 = blockIdx.x * 128;

    float acc[4][4][4];
#pragma unroll
    for (int i = 0; i < 4; i++)
#pragma unroll
        for (int j = 0; j < 4; j++)
#pragma unroll
            for (int r = 0; r < 4; r++) acc[i][j][r] = 0.f;

    // A slots: 2 per thread, 8 floats each (row, kg8)
    int arow[2], akg[2];
    // B slots: 2 per thread (kp, c4), loads rows 2kp & 2kp+1
    int bkp[2], bc4[2];
#pragma unroll
    for (int s = 0; s < 2; s++) {
        int idx = t + s * 256;
        arow[s] = idx >> 2;  akg[s] = (idx & 3) * 8;
        bkp[s]  = idx >> 5;  bc4[s] = (idx & 31) * 4;
    }

    float4 xa[2][2], wb[2][2];
#pragma unroll
    for (int s = 0; s < 2; s++) {
        const float* pa = X + (size_t)(row0 + arow[s]) * DIMD + akg[s];
        xa[s][0] = *(const float4*)pa;
        xa[s][1] = *(const float4*)(pa + 4);
        const float* pb = W + (size_t)(2 * bkp[s]) * DIMD + col0 + bc4[s];
        wb[s][0] = *(const float4*)pb;
        wb[s][1] = *(const float4*)(pb + DIMD);
    }

    for (int p = 0; p < 32; p++) {
#pragma unroll
        for (int s = 0; s < 2; s++) {
            *(uint4*)&As[arow[s]][(akg[s] >> 1)] = make_uint4(
                f2h2(xa[s][0].x, xa[s][0].y), f2h2(xa[s][0].z, xa[s][0].w),
                f2h2(xa[s][1].x, xa[s][1].y), f2h2(xa[s][1].z, xa[s][1].w));
            *(uint4*)&Bs[bkp[s]][bc4[s]] = make_uint4(
                f2h2(wb[s][0].x, wb[s][1].x), f2h2(wb[s][0].y, wb[s][1].y),
                f2h2(wb[s][0].z, wb[s][1].z), f2h2(wb[s][0].w, wb[s][1].w));
        }
        __syncthreads();
        if (p + 1 < 32) {
            int k0 = (p + 1) * 32;
#pragma unroll
            for (int s = 0; s < 2; s++) {
                const float* pa = X + (size_t)(row0 + arow[s]) * DIMD + k0 + akg[s];
                xa[s][0] = *(const float4*)pa;
                xa[s][1] = *(const float4*)(pa + 4);
                const float* pb = W + (size_t)(k0 + 2 * bkp[s]) * DIMD + col0 + bc4[s];
                wb[s][0] = *(const float4*)pb;
                wb[s][1] = *(const float4*)(pb + DIMD);
            }
        }
#pragma unroll
        for (int ks = 0; ks < 2; ks++) {
            int kb = ks * 8;
            unsigned a[4][4], b[4][2];
#pragma unroll
            for (int mt = 0; mt < 4; mt++) {
                int mr = wm * 64 + mt * 16 + g;
                a[mt][0] = As[mr][kb + tq];
                a[mt][1] = As[mr + 8][kb + tq];
                a[mt][2] = As[mr][kb + tq + 4];
                a[mt][3] = As[mr + 8][kb + tq + 4];
            }
#pragma unroll
            for (int nt = 0; nt < 4; nt++) {
                int nc = wn * 32 + nt * 8 + g;
                b[nt][0] = Bs[kb + tq][nc];
                b[nt][1] = Bs[kb + tq + 4][nc];
            }
#pragma unroll
            for (int mt = 0; mt < 4; mt++)
#pragma unroll
                for (int nt = 0; nt < 4; nt++)
                    mma_f16(acc[mt][nt], a[mt], b[nt], acc[mt][nt]);
        }
        __syncthreads();
    }

#pragma unroll
    for (int mt = 0; mt < 4; mt++) {
#pragma unroll
        for (int nt = 0; nt < 4; nt++) {
            int c = col0 + wn * 32 + nt * 8 + 2 * tq;
#pragma unroll
            for (int half = 0; half < 2; half++) {
                int m = row0 + wm * 64 + mt * 16 + g + half * 8;
                float2 val = make_float2(acc[mt][nt][half * 2], acc[mt][nt][half * 2 + 1]);
                if (MODE == 0) {
                    int bi = m >> 11, n = m & 2047, h = c >> 6, d = c & 63;
                    *(float2*)&Y[(((size_t)(bi * HEADS + h) * SEQ + n) << 6) + d] = val;
                } else {
                    float2 bv = *(const float2*)&bo[c];
                    float2 rv = *(const float2*)&resid[(size_t)m * DIMD + c];
                    val.x += bv.x + rv.x;
                    val.y += bv.y + rv.y;
                    *(float2*)&Y[(size_t)m * DIMD + c] = val;
                }
            }
        }
    }
}

// ---------------- partial RoPE on first 32 dims of q,k,v -------------------
__global__ void rope_kernel(const float* __restrict__ rope) {
    int idx = blockIdx.x * blockDim.x + threadIdx.x;
    if (idx >= BH * SEQ * 16) return;
    int p = idx & 15;
    int n = (idx >> 4) & (SEQ - 1);
    int z = idx >> 15;
    size_t base = ((size_t)z * SEQ + n) * DH;
    float r1 = rope[n * ROT + p];
    float r2 = rope[n * ROT + p + 16];
    float c1 = cosf(r1), s1 = sinf(r1);
    float c2 = cosf(r2), s2 = sinf(r2);
    float* arrs[3] = {g_Q, g_K, g_V};
#pragma unroll
    for (int a = 0; a < 3; a++) {
        float t0 = arrs[a][base + p];
        float t1 = arrs[a][base + p + 16];
        arrs[a][base + p]      = t0 * c1 - t1 * s1;
        arrs[a][base + p + 16] = t1 * c2 + t0 * s2;
    }
}

// ============ P_unnorm = exp(scale * Q K^T) fp16 MMA + partial sums ========
// Block 128x128, 8 warps 2(m)x4(n).
__global__ __launch_bounds__(256) void qk_exp(float* __restrict__ S) {
    __shared__ unsigned Qs[128][36];   // [m][kp], 32 used
    __shared__ unsigned Ks[128][36];   // [n][kp], 32 used
    __shared__ float part[128][4];

    int t = threadIdx.x;
    int w = t >> 5, lane = t & 31, g = lane >> 2, tq = lane & 3;
    int wm = w & 1, wn = w >> 1;
    int z = blockIdx.z;
    int i0 = blockIdx.y * 128, j0 = blockIdx.x * 128;
    const float* Qb = g_Q + (size_t)z * SEQ * DH;
    const float* Kb = g_K + (size_t)z * SEQ * DH;

    // 128x64 tiles: 1024 slots of 8 floats each -> 4 per thread
#pragma unroll
    for (int s = 0; s < 4; s++) {
        int idx = t + s * 256;
        int row = idx >> 3, kg = (idx & 7) * 8;
        const float* pq = Qb + (size_t)(i0 + row) * DH + kg;
        float4 q0 = *(const float4*)pq, q1 = *(const float4*)(pq + 4);
        *(uint4*)&Qs[row][(kg >> 1)] = make_uint4(
            f2h2(q0.x, q0.y), f2h2(q0.z, q0.w), f2h2(q1.x, q1.y), f2h2(q1.z, q1.w));
        const float* pk = Kb + (size_t)(j0 + row) * DH + kg;
        float4 k0 = *(const float4*)pk, k1 = *(const float4*)(pk + 4);
        *(uint4*)&Ks[row][(kg >> 1)] = make_uint4(
            f2h2(k0.x, k0.y), f2h2(k0.z, k0.w), f2h2(k1.x, k1.y), f2h2(k1.z, k1.w));
    }
    __syncthreads();

    float acc[4][4][4];
#pragma unroll
    for (int i = 0; i < 4; i++)
#pragma unroll
        for (int j = 0; j < 4; j++)
#pragma unroll
            for (int r = 0; r < 4; r++) acc[i][j][r] = 0.f;

#pragma unroll
    for (int ks = 0; ks < 4; ks++) {
        int kb = ks * 8;
        unsigned a[4][4], b[4][2];
#pragma unroll
        for (int mt = 0; mt < 4; mt++) {
            int mr = wm * 64 + mt * 16 + g;
            a[mt][0] = Qs[mr][kb + tq];
            a[mt][1] = Qs[mr + 8][kb + tq];
            a[mt][2] = Qs[mr][kb + tq + 4];
            a[mt][3] = Qs[mr + 8][kb + tq + 4];
        }
#pragma unroll
        for (int nt = 0; nt < 4; nt++) {
            int nr = wn * 32 + nt * 8 + g;
            b[nt][0] = Ks[nr][kb + tq];
            b[nt][1] = Ks[nr][kb + tq + 4];
        }
#pragma unroll
        for (int mt = 0; mt < 4; mt++)
#pragma unroll
            for (int nt = 0; nt < 4; nt++)
                mma_f16(acc[mt][nt], a[mt], b[nt], acc[mt][nt]);
    }

    float* Sb = S + (size_t)z * SEQ * SEQ;
#pragma unroll
    for (int mt = 0; mt < 4; mt++) {
#pragma unroll
        for (int half = 0; half < 2; half++) {
            float rpart = 0.f;
#pragma unroll
            for (int nt = 0; nt < 4; nt++) {
                float p0 = __expf(acc[mt][nt][half * 2]     * 0.125f);
                float p1 = __expf(acc[mt][nt][half * 2 + 1] * 0.125f);
                rpart += p0 + p1;
                int c = j0 + wn * 32 + nt * 8 + 2 * tq;
                int m = i0 + wm * 64 + mt * 16 + g + half * 8;
                *(float2*)&Sb[(size_t)m * SEQ + c] = make_float2(p0, p1);
            }
            rpart += __shfl_xor_sync(0xffffffffu, rpart, 1);
            rpart += __shfl_xor_sync(0xffffffffu, rpart, 2);
            if (tq == 0) {
                int row = wm * 64 + mt * 16 + half * 8 + g;
                part[row][wn] = rpart;
            }
        }
    }
    __syncthreads();
    if (t < 128) {
        float s = part[t][0] + part[t][1] + part[t][2] + part[t][3];
        g_part[(size_t)blockIdx.x * NROWS + (size_t)z * SEQ + i0 + t] = s;
    }
}

// ---------------- inv = 1 / sum(partials) ----------------
__global__ void reduce_inv() {
    size_t i = (size_t)blockIdx.x * blockDim.x + threadIdx.x;
    if (i >= NROWS) return;
    float s = 0.f;
#pragma unroll
    for (int j = 0; j < 16; j++) s += g_part[(size_t)j * NROWS + i];
    g_inv[i] = 1.f / s;
}

// ============ normalize attn in place + O = P @ V (fp16 MMA) ==============
// Block 128 rows, j-loop 128. 8 warps 2(m)x4(n), warp tile 64x16.
__global__ __launch_bounds__(256) void pv_norm(float* __restrict__ S) {
    extern __shared__ char smem_raw[];
    unsigned (*Ps)[68] = (unsigned (*)[68])smem_raw;                   // [m][kp] 64 used
    unsigned (*Vs)[72] = (unsigned (*)[72])(smem_raw + 128*68*4);      // [kp][n] 64x72
    float* inv_s       = (float*)(smem_raw + 128*68*4 + 64*72*4);      // 128

    int t = threadIdx.x;
    int w = t >> 5, lane = t & 31, g = lane >> 2, tq = lane & 3;
    int wm = w & 1, wn = w >> 1;
    int z = blockIdx.y;
    int i0 = blockIdx.x * 128;
    float* Sb = S + (size_t)z * SEQ * SEQ;
    const float* Vb = g_V + (size_t)z * SEQ * DH;

    if (t < 128) inv_s[t] = g_inv[(size_t)z * SEQ + i0 + t];

    float acc[4][2][4];
#pragma unroll
    for (int i = 0; i < 4; i++)
#pragma unroll
        for (int j = 0; j < 2; j++)
#pragma unroll
            for (int r = 0; r < 4; r++) acc[i][j][r] = 0.f;

    for (int j0 = 0; j0 < SEQ; j0 += 128) {
        __syncthreads();
        // P tile 128x128: 2048 slots of 8 -> 8 per thread; normalize + writeback
#pragma unroll
        for (int s = 0; s < 8; s++) {
            int idx = t + s * 256;
            int m = idx >> 4, kg = (idx & 15) * 8;
            float* gp = Sb + (size_t)(i0 + m) * SEQ + j0 + kg;
            float4 p0 = *(float4*)gp, p1 = *(float4*)(gp + 4);
            float iv = inv_s[m];
            p0.x *= iv; p0.y *= iv; p0.z *= iv; p0.w *= iv;
            p1.x *= iv; p1.y *= iv; p1.z *= iv; p1.w *= iv;
            *(float4*)gp = p0; *(float4*)(gp + 4) = p1;
            *(uint4*)&Ps[m][(kg >> 1)] = make_uint4(
                f2h2(p0.x, p0.y), f2h2(p0.z, p0.w), f2h2(p1.x, p1.y), f2h2(p1.z, p1.w));
        }
        // V tile 128x64 -> Vs[kp][n] pairs of adjacent j rows: 1024 slots -> 4/thread
#pragma unroll
        for (int s = 0; s < 4; s++) {
            int idx = t + s * 256;
            int kp = idx >> 4, c4 = (idx & 15) * 4;
            const float* pv = Vb + (size_t)(j0 + 2 * kp) * DH + c4;
            float4 v0 = *(const float4*)pv;
            float4 v1 = *(const float4*)(pv + DH);
            *(uint4*)&Vs[kp][c4] = make_uint4(
                f2h2(v0.x, v1.x), f2h2(v0.y, v1.y), f2h2(v0.z, v1.z), f2h2(v0.w, v1.w));
        }
        __syncthreads();
#pragma unroll
        for (int ks = 0; ks < 8; ks++) {
            int kb = ks * 8;
            unsigned a[4][4], b[2][2];
#pragma unroll
            for (int mt = 0; mt < 4; mt++) {
                int mr = wm * 64 + mt * 16 + g;
                a[mt][0] = Ps[mr][kb + tq];
                a[mt][1] = Ps[mr + 8][kb + tq];
                a[mt][2] = Ps[mr][kb + tq + 4];
                a[mt][3] = Ps[mr + 8][kb + tq + 4];
            }
#pragma unroll
            for (int nt = 0; nt < 2; nt++) {
                int nc = wn * 16 + nt * 8 + g;
                b[nt][0] = Vs[kb + tq][nc];
                b[nt][1] = Vs[kb + tq + 4][nc];
            }
#pragma unroll
            for (int mt = 0; mt < 4; mt++)
#pragma unroll
                for (int nt = 0; nt < 2; nt++)
                    mma_f16(acc[mt][nt], a[mt], b[nt], acc[mt][nt]);
        }
    }

    int bi = z >> 4, h = z & 15;
#pragma unroll
    for (int mt = 0; mt < 4; mt++) {
#pragma unroll
        for (int nt = 0; nt < 2; nt++) {
            int c = wn * 16 + nt * 8 + 2 * tq;
#pragma unroll
            for (int half = 0; half < 2; half++) {
                int m = i0 + wm * 64 + mt * 16 + g + half * 8;
                float2 val = make_float2(acc[mt][nt][half * 2], acc[mt][nt][half * 2 + 1]);
                *(float2*)&g_O[((size_t)bi * SEQ + m) * DIMD + h * 64 + c] = val;
            }
        }
    }
}

// ---------------------------- launcher -------------------------------------
extern "C" void kernel_launch(void* const* d_in, const int* in_sizes, int n_in,
                              void* d_out, int out_size) {
    const float* x    = (const float*)d_in[0];
    const float* rope = (const float*)d_in[1];
    const float* Wq   = (const float*)d_in[2];
    const float* Wk   = (const float*)d_in[3];
    const float* Wv   = (const float*)d_in[4];
    const float* Wo   = (const float*)d_in[5];
    const float* bo   = (const float*)d_in[6];

    float* out  = (float*)d_out;
    float* attn = out + OUT_ELEMS;

    float *Qp, *Kp, *Vp, *Op;
    cudaGetSymbolAddress((void**)&Qp, g_Q);
    cudaGetSymbolAddress((void**)&Kp, g_K);
    cudaGetSymbolAddress((void**)&Vp, g_V);
    cudaGetSymbolAddress((void**)&Op, g_O);

    const int PV_SMEM = 128 * 68 * 4 + 64 * 72 * 4 + 128 * 4;   // 53760
    cudaFuncSetAttribute(pv_norm, cudaFuncAttributeMaxDynamicSharedMemorySize, PV_SMEM);

    gemm1024_f16<0><<<dim3(8, 64), 256>>>(x, Wq, nullptr, nullptr, Qp);
    gemm1024_f16<0><<<dim3(8, 64), 256>>>(x, Wk, nullptr, nullptr, Kp);
    gemm1024_f16<0><<<dim3(8, 64), 256>>>(x, Wv, nullptr, nullptr, Vp);

    rope_kernel<<<(BH * SEQ * 16) / 256, 256>>>(rope);

    qk_exp<<<dim3(16, 16, 64), 256>>>(attn);

    reduce_inv<<<(int)(NROWS / 256), 256>>>();

    pv_norm<<<dim3(16, 64), 256, PV_SMEM>>>(attn);

    gemm1024_f16<1><<<dim3(8, 64), 256>>>(Op, Wo, bo, x, out);
}

// round 7
// speedup vs baseline: 3.9525x; 1.0912x over previous
#include <cuda_runtime.h>
#include <cuda_fp16.h>
#include <math.h>
#include <stdint.h>

#define BB     4
#define SEQ    2048
#define DIMD   1024
#define HEADS  16
#define DH     64
#define ROT    32
#define BH     (BB*HEADS)          // 64
#define MROWS  (BB*SEQ)            // 8192
#define OUT_ELEMS ((size_t)MROWS*DIMD)

// ---------------- scratch ----------------
__device__ float g_Q[(size_t)BH*SEQ*DH];
__device__ float g_K[(size_t)BH*SEQ*DH];
__device__ float g_V[(size_t)BH*SEQ*DH];
__device__ float g_O[(size_t)MROWS*DIMD];

// ---------------- helpers ----------------
__device__ __forceinline__ unsigned f2h2(float a, float b) {
    unsigned u;
    asm("cvt.rn.f16x2.f32 %0, %2, %1;" : "=r"(u) : "f"(a), "f"(b));
    return u;
}

// fp16 MMA m16n8k16, f32 accumulate
__device__ __forceinline__ void mma_f16(float d[4], const unsigned a[4],
                                        const unsigned b[2], const float c[4]) {
    asm volatile(
        "mma.sync.aligned.m16n8k16.row.col.f32.f16.f16.f32 "
        "{%0,%1,%2,%3}, {%4,%5,%6,%7}, {%8,%9}, {%10,%11,%12,%13};"
        : "=f"(d[0]), "=f"(d[1]), "=f"(d[2]), "=f"(d[3])
        : "r"(a[0]), "r"(a[1]), "r"(a[2]), "r"(a[3]),
          "r"(b[0]), "r"(b[1]),
          "f"(c[0]), "f"(c[1]), "f"(c[2]), "f"(c[3]));
}

// ============ 128x128x32 fp16 block GEMM (proj / final) ====================
template <int MODE>
__global__ __launch_bounds__(256) void gemm1024_f16(
    const float* __restrict__ X, const float* __restrict__ W,
    const float* __restrict__ bo, const float* __restrict__ resid,
    float* __restrict__ Y)
{
    __shared__ unsigned As[128][20];
    __shared__ unsigned Bs[16][136];
    int t = threadIdx.x;
    int w = t >> 5, lane = t & 31, g = lane >> 2, tq = lane & 3;
    int wm = w & 1, wn = w >> 1;
    int row0 = blockIdx.y * 128, col0 = blockIdx.x * 128;

    float acc[4][4][4];
#pragma unroll
    for (int i = 0; i < 4; i++)
#pragma unroll
        for (int j = 0; j < 4; j++)
#pragma unroll
            for (int r = 0; r < 4; r++) acc[i][j][r] = 0.f;

    int arow[2], akg[2], bkp[2], bc4[2];
#pragma unroll
    for (int s = 0; s < 2; s++) {
        int idx = t + s * 256;
        arow[s] = idx >> 2;  akg[s] = (idx & 3) * 8;
        bkp[s]  = idx >> 5;  bc4[s] = (idx & 31) * 4;
    }

    float4 xa[2][2], wb[2][2];
#pragma unroll
    for (int s = 0; s < 2; s++) {
        const float* pa = X + (size_t)(row0 + arow[s]) * DIMD + akg[s];
        xa[s][0] = *(const float4*)pa;
        xa[s][1] = *(const float4*)(pa + 4);
        const float* pb = W + (size_t)(2 * bkp[s]) * DIMD + col0 + bc4[s];
        wb[s][0] = *(const float4*)pb;
        wb[s][1] = *(const float4*)(pb + DIMD);
    }

    for (int p = 0; p < 32; p++) {
#pragma unroll
        for (int s = 0; s < 2; s++) {
            *(uint4*)&As[arow[s]][(akg[s] >> 1)] = make_uint4(
                f2h2(xa[s][0].x, xa[s][0].y), f2h2(xa[s][0].z, xa[s][0].w),
                f2h2(xa[s][1].x, xa[s][1].y), f2h2(xa[s][1].z, xa[s][1].w));
            *(uint4*)&Bs[bkp[s]][bc4[s]] = make_uint4(
                f2h2(wb[s][0].x, wb[s][1].x), f2h2(wb[s][0].y, wb[s][1].y),
                f2h2(wb[s][0].z, wb[s][1].z), f2h2(wb[s][0].w, wb[s][1].w));
        }
        __syncthreads();
        if (p + 1 < 32) {
            int k0 = (p + 1) * 32;
#pragma unroll
            for (int s = 0; s < 2; s++) {
                const float* pa = X + (size_t)(row0 + arow[s]) * DIMD + k0 + akg[s];
                xa[s][0] = *(const float4*)pa;
                xa[s][1] = *(const float4*)(pa + 4);
                const float* pb = W + (size_t)(k0 + 2 * bkp[s]) * DIMD + col0 + bc4[s];
                wb[s][0] = *(const float4*)pb;
                wb[s][1] = *(const float4*)(pb + DIMD);
            }
        }
#pragma unroll
        for (int ks = 0; ks < 2; ks++) {
            int kb = ks * 8;
            unsigned a[4][4], b[4][2];
#pragma unroll
            for (int mt = 0; mt < 4; mt++) {
                int mr = wm * 64 + mt * 16 + g;
                a[mt][0] = As[mr][kb + tq];
                a[mt][1] = As[mr + 8][kb + tq];
                a[mt][2] = As[mr][kb + tq + 4];
                a[mt][3] = As[mr + 8][kb + tq + 4];
            }
#pragma unroll
            for (int nt = 0; nt < 4; nt++) {
                int nc = wn * 32 + nt * 8 + g;
                b[nt][0] = Bs[kb + tq][nc];
                b[nt][1] = Bs[kb + tq + 4][nc];
            }
#pragma unroll
            for (int mt = 0; mt < 4; mt++)
#pragma unroll
                for (int nt = 0; nt < 4; nt++)
                    mma_f16(acc[mt][nt], a[mt], b[nt], acc[mt][nt]);
        }
        __syncthreads();
    }

#pragma unroll
    for (int mt = 0; mt < 4; mt++) {
#pragma unroll
        for (int nt = 0; nt < 4; nt++) {
            int c = col0 + wn * 32 + nt * 8 + 2 * tq;
#pragma unroll
            for (int half = 0; half < 2; half++) {
                int m = row0 + wm * 64 + mt * 16 + g + half * 8;
                float2 val = make_float2(acc[mt][nt][half * 2], acc[mt][nt][half * 2 + 1]);
                if (MODE == 0) {
                    int bi = m >> 11, n = m & 2047, h = c >> 6, d = c & 63;
                    *(float2*)&Y[(((size_t)(bi * HEADS + h) * SEQ + n) << 6) + d] = val;
                } else {
                    float2 bv = *(const float2*)&bo[c];
                    float2 rv = *(const float2*)&resid[(size_t)m * DIMD + c];
                    val.x += bv.x + rv.x;
                    val.y += bv.y + rv.y;
                    *(float2*)&Y[(size_t)m * DIMD + c] = val;
                }
            }
        }
    }
}

// ---------------- partial RoPE on first 32 dims of q,k,v -------------------
__global__ void rope_kernel(const float* __restrict__ rope) {
    int idx = blockIdx.x * blockDim.x + threadIdx.x;
    if (idx >= BH * SEQ * 16) return;
    int p = idx & 15;
    int n = (idx >> 4) & (SEQ - 1);
    int z = idx >> 15;
    size_t base = ((size_t)z * SEQ + n) * DH;
    float r1 = rope[n * ROT + p];
    float r2 = rope[n * ROT + p + 16];
    float c1 = cosf(r1), s1 = sinf(r1);
    float c2 = cosf(r2), s2 = sinf(r2);
    float* arrs[3] = {g_Q, g_K, g_V};
#pragma unroll
    for (int a = 0; a < 3; a++) {
        float t0 = arrs[a][base + p];
        float t1 = arrs[a][base + p + 16];
        arrs[a][base + p]      = t0 * c1 - t1 * s1;
        arrs[a][base + p + 16] = t1 * c2 + t0 * s2;
    }
}

// ================= fused flash attention ====================================
// One CTA per (z, i-block of 128 rows). 8 warps 2(m) x 4(n).
// Pass 1: QK+exp -> row sums (registers). Pass 2: QK+exp*inv -> write attn,
// P fragments straight from accumulator -> PV MMA; cross-warp O reduce.
__global__ __launch_bounds__(256) void fused_attn(float* __restrict__ S) {
    extern __shared__ char smraw[];
    unsigned (*Qs)[36] = (unsigned (*)[36])smraw;                    // 18432 B
    unsigned (*Ks)[36] = (unsigned (*)[36])(smraw + 18432);          // 18432 B
    unsigned (*Vs)[72] = (unsigned (*)[72])(smraw + 36864);          // 18432 B
    float* inv_s       = (float*)(smraw + 55296);                    // 512 B
    float (*part)[4]   = (float (*)[4])(smraw + 55808);              // 2048 B
    float (*obuf)[66]  = (float (*)[66])smraw;                       // 33792 B (overlay)

    int t = threadIdx.x;
    int w = t >> 5, lane = t & 31, g = lane >> 2, tq = lane & 3;
    int wm = w & 1, wn = w >> 1;
    int z = blockIdx.y;
    int i0 = blockIdx.x * 128;
    const float* Qb = g_Q + (size_t)z * SEQ * DH;
    const float* Kb = g_K + (size_t)z * SEQ * DH;
    const float* Vb = g_V + (size_t)z * SEQ * DH;
    float* Sb = S + (size_t)z * SEQ * SEQ;

    // ---- load Q tile once (128x64) ----
#pragma unroll
    for (int s = 0; s < 4; s++) {
        int idx = t + s * 256;
        int row = idx >> 3, kg = (idx & 7) * 8;
        const float* pq = Qb + (size_t)(i0 + row) * DH + kg;
        float4 q0 = *(const float4*)pq, q1 = *(const float4*)(pq + 4);
        *(uint4*)&Qs[row][(kg >> 1)] = make_uint4(
            f2h2(q0.x, q0.y), f2h2(q0.z, q0.w), f2h2(q1.x, q1.y), f2h2(q1.z, q1.w));
    }

    // ======== PASS 1: row sums ========
    float rsum[4][2];
#pragma unroll
    for (int i = 0; i < 4; i++) { rsum[i][0] = 0.f; rsum[i][1] = 0.f; }

    for (int j0 = 0; j0 < SEQ; j0 += 128) {
        __syncthreads();
#pragma unroll
        for (int s = 0; s < 4; s++) {
            int idx = t + s * 256;
            int row = idx >> 3, kg = (idx & 7) * 8;
            const float* pk = Kb + (size_t)(j0 + row) * DH + kg;
            float4 k0 = *(const float4*)pk, k1 = *(const float4*)(pk + 4);
            *(uint4*)&Ks[row][(kg >> 1)] = make_uint4(
                f2h2(k0.x, k0.y), f2h2(k0.z, k0.w), f2h2(k1.x, k1.y), f2h2(k1.z, k1.w));
        }
        __syncthreads();

        float acc[4][4][4];
#pragma unroll
        for (int i = 0; i < 4; i++)
#pragma unroll
            for (int j = 0; j < 4; j++)
#pragma unroll
                for (int r = 0; r < 4; r++) acc[i][j][r] = 0.f;

#pragma unroll
        for (int ks = 0; ks < 4; ks++) {
            int kb = ks * 8;
            unsigned a[4][4], b[4][2];
#pragma unroll
            for (int mt = 0; mt < 4; mt++) {
                int mr = wm * 64 + mt * 16 + g;
                a[mt][0] = Qs[mr][kb + tq];
                a[mt][1] = Qs[mr + 8][kb + tq];
                a[mt][2] = Qs[mr][kb + tq + 4];
                a[mt][3] = Qs[mr + 8][kb + tq + 4];
            }
#pragma unroll
            for (int nt = 0; nt < 4; nt++) {
                int nr = wn * 32 + nt * 8 + g;
                b[nt][0] = Ks[nr][kb + tq];
                b[nt][1] = Ks[nr][kb + tq + 4];
            }
#pragma unroll
            for (int mt = 0; mt < 4; mt++)
#pragma unroll
                for (int nt = 0; nt < 4; nt++)
                    mma_f16(acc[mt][nt], a[mt], b[nt], acc[mt][nt]);
        }
#pragma unroll
        for (int mt = 0; mt < 4; mt++)
#pragma unroll
            for (int nt = 0; nt < 4; nt++) {
                rsum[mt][0] += __expf(acc[mt][nt][0] * 0.125f)
                             + __expf(acc[mt][nt][1] * 0.125f);
                rsum[mt][1] += __expf(acc[mt][nt][2] * 0.125f)
                             + __expf(acc[mt][nt][3] * 0.125f);
            }
    }

    // reduce rsum -> inv_s
#pragma unroll
    for (int mt = 0; mt < 4; mt++)
#pragma unroll
        for (int half = 0; half < 2; half++) {
            float r = rsum[mt][half];
            r += __shfl_xor_sync(0xffffffffu, r, 1);
            r += __shfl_xor_sync(0xffffffffu, r, 2);
            if (tq == 0) part[wm * 64 + mt * 16 + half * 8 + g][wn] = r;
        }
    __syncthreads();
    if (t < 128) inv_s[t] = 1.f / (part[t][0] + part[t][1] + part[t][2] + part[t][3]);

    // ======== PASS 2: normalized attn write + PV ========
    float accO[4][8][4];
#pragma unroll
    for (int i = 0; i < 4; i++)
#pragma unroll
        for (int j = 0; j < 8; j++)
#pragma unroll
            for (int r = 0; r < 4; r++) accO[i][j][r] = 0.f;

    for (int j0 = 0; j0 < SEQ; j0 += 128) {
        __syncthreads();
#pragma unroll
        for (int s = 0; s < 4; s++) {
            int idx = t + s * 256;
            int row = idx >> 3, kg = (idx & 7) * 8;
            const float* pk = Kb + (size_t)(j0 + row) * DH + kg;
            float4 k0 = *(const float4*)pk, k1 = *(const float4*)(pk + 4);
            *(uint4*)&Ks[row][(kg >> 1)] = make_uint4(
                f2h2(k0.x, k0.y), f2h2(k0.z, k0.w), f2h2(k1.x, k1.y), f2h2(k1.z, k1.w));
        }
#pragma unroll
        for (int s = 0; s < 4; s++) {
            int idx = t + s * 256;
            int kp = idx >> 4, c4 = (idx & 15) * 4;
            const float* pv = Vb + (size_t)(j0 + 2 * kp) * DH + c4;
            float4 v0 = *(const float4*)pv;
            float4 v1 = *(const float4*)(pv + DH);
            *(uint4*)&Vs[kp][c4] = make_uint4(
                f2h2(v0.x, v1.x), f2h2(v0.y, v1.y), f2h2(v0.z, v1.z), f2h2(v0.w, v1.w));
        }
        __syncthreads();

        float acc[4][4][4];
#pragma unroll
        for (int i = 0; i < 4; i++)
#pragma unroll
            for (int j = 0; j < 4; j++)
#pragma unroll
                for (int r = 0; r < 4; r++) acc[i][j][r] = 0.f;

#pragma unroll
        for (int ks = 0; ks < 4; ks++) {
            int kb = ks * 8;
            unsigned a[4][4], b[4][2];
#pragma unroll
            for (int mt = 0; mt < 4; mt++) {
                int mr = wm * 64 + mt * 16 + g;
                a[mt][0] = Qs[mr][kb + tq];
                a[mt][1] = Qs[mr + 8][kb + tq];
                a[mt][2] = Qs[mr][kb + tq + 4];
                a[mt][3] = Qs[mr + 8][kb + tq + 4];
            }
#pragma unroll
            for (int nt = 0; nt < 4; nt++) {
                int nr = wn * 32 + nt * 8 + g;
                b[nt][0] = Ks[nr][kb + tq];
                b[nt][1] = Ks[nr][kb + tq + 4];
            }
#pragma unroll
            for (int mt = 0; mt < 4; mt++)
#pragma unroll
                for (int nt = 0; nt < 4; nt++)
                    mma_f16(acc[mt][nt], a[mt], b[nt], acc[mt][nt]);
        }

        // exp * inv, write attn
#pragma unroll
        for (int mt = 0; mt < 4; mt++) {
            int mr0 = wm * 64 + mt * 16 + g;
            float iv0 = inv_s[mr0];
            float iv1 = inv_s[mr0 + 8];
#pragma unroll
            for (int nt = 0; nt < 4; nt++) {
                acc[mt][nt][0] = __expf(acc[mt][nt][0] * 0.125f) * iv0;
                acc[mt][nt][1] = __expf(acc[mt][nt][1] * 0.125f) * iv0;
                acc[mt][nt][2] = __expf(acc[mt][nt][2] * 0.125f) * iv1;
                acc[mt][nt][3] = __expf(acc[mt][nt][3] * 0.125f) * iv1;
                int c = j0 + wn * 32 + nt * 8 + 2 * tq;
                *(float2*)&Sb[(size_t)(i0 + mr0) * SEQ + c] =
                    make_float2(acc[mt][nt][0], acc[mt][nt][1]);
                *(float2*)&Sb[(size_t)(i0 + mr0 + 8) * SEQ + c] =
                    make_float2(acc[mt][nt][2], acc[mt][nt][3]);
            }
        }

        // PV: P fragments direct from acc; warp's k-slice = wn*32 (2 steps of 16)
#pragma unroll
        for (int s = 0; s < 2; s++) {
            unsigned aP[4][4], b[8][2];
#pragma unroll
            for (int mt = 0; mt < 4; mt++) {
                aP[mt][0] = f2h2(acc[mt][2*s][0],   acc[mt][2*s][1]);
                aP[mt][1] = f2h2(acc[mt][2*s][2],   acc[mt][2*s][3]);
                aP[mt][2] = f2h2(acc[mt][2*s+1][0], acc[mt][2*s+1][1]);
                aP[mt][3] = f2h2(acc[mt][2*s+1][2], acc[mt][2*s+1][3]);
            }
#pragma unroll
            for (int nt = 0; nt < 8; nt++) {
                int nc = nt * 8 + g;
                b[nt][0] = Vs[wn * 16 + s * 8 + tq][nc];
                b[nt][1] = Vs[wn * 16 + s * 8 + tq + 4][nc];
            }
#pragma unroll
            for (int mt = 0; mt < 4; mt++)
#pragma unroll
                for (int nt = 0; nt < 8; nt++)
                    mma_f16(accO[mt][nt], aP[mt], b[nt], accO[mt][nt]);
        }
    }

    // ---- cross-warp O reduce (over wn) via smem ----
    __syncthreads();   // done with Qs/Ks reads; obuf overlays them
#pragma unroll
    for (int p = 0; p < 4; p++) {
        if (wn == p) {
#pragma unroll
            for (int mt = 0; mt < 4; mt++) {
                int r0 = wm * 64 + mt * 16 + g;
#pragma unroll
                for (int nt = 0; nt < 8; nt++) {
                    int c = nt * 8 + 2 * tq;
                    if (p == 0) {
                        *(float2*)&obuf[r0][c] = make_float2(accO[mt][nt][0], accO[mt][nt][1]);
                        *(float2*)&obuf[r0 + 8][c] = make_float2(accO[mt][nt][2], accO[mt][nt][3]);
                    } else {
                        float2 o0 = *(float2*)&obuf[r0][c];
                        float2 o1 = *(float2*)&obuf[r0 + 8][c];
                        o0.x += accO[mt][nt][0]; o0.y += accO[mt][nt][1];
                        o1.x += accO[mt][nt][2]; o1.y += accO[mt][nt][3];
                        *(float2*)&obuf[r0][c] = o0;
                        *(float2*)&obuf[r0 + 8][c] = o1;
                    }
                }
            }
        }
        __syncthreads();
    }

    // write O: [b, n, h*64+d]
    int bi = z >> 4, h = z & 15;
#pragma unroll
    for (int it = 0; it < 8; it++) {
        int idx = t + it * 256;
        int m = idx >> 4, c4 = (idx & 15) * 4;
        float4 v = make_float4(obuf[m][c4], obuf[m][c4 + 1], obuf[m][c4 + 2], obuf[m][c4 + 3]);
        *(float4*)&g_O[((size_t)bi * SEQ + i0 + m) * DIMD + h * 64 + c4] = v;
    }
}

// ---------------------------- launcher -------------------------------------
extern "C" void kernel_launch(void* const* d_in, const int* in_sizes, int n_in,
                              void* d_out, int out_size) {
    const float* x    = (const float*)d_in[0];
    const float* rope = (const float*)d_in[1];
    const float* Wq   = (const float*)d_in[2];
    const float* Wk   = (const float*)d_in[3];
    const float* Wv   = (const float*)d_in[4];
    const float* Wo   = (const float*)d_in[5];
    const float* bo   = (const float*)d_in[6];

    float* out  = (float*)d_out;
    float* attn = out + OUT_ELEMS;

    float *Qp, *Kp, *Vp, *Op;
    cudaGetSymbolAddress((void**)&Qp, g_Q);
    cudaGetSymbolAddress((void**)&Kp, g_K);
    cudaGetSymbolAddress((void**)&Vp, g_V);
    cudaGetSymbolAddress((void**)&Op, g_O);

    const int FA_SMEM = 57856;
    cudaFuncSetAttribute(fused_attn, cudaFuncAttributeMaxDynamicSharedMemorySize, FA_SMEM);

    gemm1024_f16<0><<<dim3(8, 64), 256>>>(x, Wq, nullptr, nullptr, Qp);
    gemm1024_f16<0><<<dim3(8, 64), 256>>>(x, Wk, nullptr, nullptr, Kp);
    gemm1024_f16<0><<<dim3(8, 64), 256>>>(x, Wv, nullptr, nullptr, Vp);

    rope_kernel<<<(BH * SEQ * 16) / 256, 256>>>(rope);

    fused_attn<<<dim3(16, 64), 256, FA_SMEM>>>(attn);

    gemm1024_f16<1><<<dim3(8, 64), 256>>>(Op, Wo, bo, x, out);
}

// round 8
// speedup vs baseline: 5.2352x; 1.3245x over previous
#include <cuda_runtime.h>
#include <cuda_fp16.h>
#include <math.h>
#include <stdint.h>

#define BB     4
#define SEQ    2048
#define DIMD   1024
#define HEADS  16
#define DH     64
#define ROT    32
#define BH     (BB*HEADS)          // 64
#define MROWS  (BB*SEQ)            // 8192
#define OUT_ELEMS ((size_t)MROWS*DIMD)

// ---------------- scratch (fp16) ----------------
__device__ __half g_Q[(size_t)BH*SEQ*DH];
__device__ __half g_K[(size_t)BH*SEQ*DH];
__device__ __half g_V[(size_t)BH*SEQ*DH];
__device__ __half g_O[(size_t)MROWS*DIMD];

// ---------------- helpers ----------------
__device__ __forceinline__ unsigned f2h2(float a, float b) {
    unsigned u;
    asm("cvt.rn.f16x2.f32 %0, %2, %1;" : "=r"(u) : "f"(a), "f"(b));
    return u;
}
__device__ __forceinline__ uint32_t smem_u32(const void* p) {
    uint32_t a;
    asm("{ .reg .u64 t; cvta.to.shared.u64 t, %1; cvt.u32.u64 %0, t; }" : "=r"(a) : "l"(p));
    return a;
}
__device__ __forceinline__ void mma_f16(float d[4], const unsigned a[4],
                                        const unsigned b[2], const float c[4]) {
    asm volatile(
        "mma.sync.aligned.m16n8k16.row.col.f32.f16.f16.f32 "
        "{%0,%1,%2,%3}, {%4,%5,%6,%7}, {%8,%9}, {%10,%11,%12,%13};"
        : "=f"(d[0]), "=f"(d[1]), "=f"(d[2]), "=f"(d[3])
        : "r"(a[0]), "r"(a[1]), "r"(a[2]), "r"(a[3]),
          "r"(b[0]), "r"(b[1]),
          "f"(c[0]), "f"(c[1]), "f"(c[2]), "f"(c[3]));
}
__device__ __forceinline__ void ldsm_x4_t(unsigned& r0, unsigned& r1,
                                          unsigned& r2, unsigned& r3, uint32_t a) {
    asm volatile("ldmatrix.sync.aligned.m8n8.x4.trans.shared.b16 {%0,%1,%2,%3}, [%4];"
                 : "=r"(r0), "=r"(r1), "=r"(r2), "=r"(r3) : "r"(a));
}
#define CPA16(d, s)   asm volatile("cp.async.ca.shared.global [%0], [%1], 16;" :: "r"(d), "l"(s))
#define CPA_COMMIT()  asm volatile("cp.async.commit_group;" ::: "memory")
#define CPA_WAIT(n)   asm volatile("cp.async.wait_group %0;" :: "n"(n) : "memory")
__device__ __forceinline__ void stcs2(float* p, float x, float y) {
    asm volatile("st.global.cs.v2.f32 [%0], {%1,%2};" :: "l"(p), "f"(x), "f"(y));
}

// ============ merged projection GEMM: z in {0,1,2} -> Q,K,V (half) ==========
__global__ __launch_bounds__(256) void proj3_f16(
    const float* __restrict__ X,
    const float* __restrict__ Wq, const float* __restrict__ Wk,
    const float* __restrict__ Wv)
{
    __shared__ unsigned As[128][20];
    __shared__ unsigned Bs[16][136];
    int t = threadIdx.x;
    int w = t >> 5, lane = t & 31, g = lane >> 2, tq = lane & 3;
    int wm = w & 1, wn = w >> 1;
    int row0 = blockIdx.y * 128, col0 = blockIdx.x * 128;
    int z = blockIdx.z;
    const float* W = (z == 0) ? Wq : (z == 1) ? Wk : Wv;
    __half* Y = (z == 0) ? g_Q : (z == 1) ? g_K : g_V;

    float acc[4][4][4];
#pragma unroll
    for (int i = 0; i < 4; i++)
#pragma unroll
        for (int j = 0; j < 4; j++)
#pragma unroll
            for (int r = 0; r < 4; r++) acc[i][j][r] = 0.f;

    int arow[2], akg[2], bkp[2], bc4[2];
#pragma unroll
    for (int s = 0; s < 2; s++) {
        int idx = t + s * 256;
        arow[s] = idx >> 2;  akg[s] = (idx & 3) * 8;
        bkp[s]  = idx >> 5;  bc4[s] = (idx & 31) * 4;
    }
    float4 xa[2][2], wb[2][2];
#pragma unroll
    for (int s = 0; s < 2; s++) {
        const float* pa = X + (size_t)(row0 + arow[s]) * DIMD + akg[s];
        xa[s][0] = *(const float4*)pa; xa[s][1] = *(const float4*)(pa + 4);
        const float* pb = W + (size_t)(2 * bkp[s]) * DIMD + col0 + bc4[s];
        wb[s][0] = *(const float4*)pb; wb[s][1] = *(const float4*)(pb + DIMD);
    }

    for (int p = 0; p < 32; p++) {
#pragma unroll
        for (int s = 0; s < 2; s++) {
            *(uint4*)&As[arow[s]][(akg[s] >> 1)] = make_uint4(
                f2h2(xa[s][0].x, xa[s][0].y), f2h2(xa[s][0].z, xa[s][0].w),
                f2h2(xa[s][1].x, xa[s][1].y), f2h2(xa[s][1].z, xa[s][1].w));
            *(uint4*)&Bs[bkp[s]][bc4[s]] = make_uint4(
                f2h2(wb[s][0].x, wb[s][1].x), f2h2(wb[s][0].y, wb[s][1].y),
                f2h2(wb[s][0].z, wb[s][1].z), f2h2(wb[s][0].w, wb[s][1].w));
        }
        __syncthreads();
        if (p + 1 < 32) {
            int k0 = (p + 1) * 32;
#pragma unroll
            for (int s = 0; s < 2; s++) {
                const float* pa = X + (size_t)(row0 + arow[s]) * DIMD + k0 + akg[s];
                xa[s][0] = *(const float4*)pa; xa[s][1] = *(const float4*)(pa + 4);
                const float* pb = W + (size_t)(k0 + 2 * bkp[s]) * DIMD + col0 + bc4[s];
                wb[s][0] = *(const float4*)pb; wb[s][1] = *(const float4*)(pb + DIMD);
            }
        }
#pragma unroll
        for (int ks = 0; ks < 2; ks++) {
            int kb = ks * 8;
            unsigned a[4][4], b[4][2];
#pragma unroll
            for (int mt = 0; mt < 4; mt++) {
                int mr = wm * 64 + mt * 16 + g;
                a[mt][0] = As[mr][kb + tq];       a[mt][1] = As[mr + 8][kb + tq];
                a[mt][2] = As[mr][kb + tq + 4];   a[mt][3] = As[mr + 8][kb + tq + 4];
            }
#pragma unroll
            for (int nt = 0; nt < 4; nt++) {
                int nc = wn * 32 + nt * 8 + g;
                b[nt][0] = Bs[kb + tq][nc];       b[nt][1] = Bs[kb + tq + 4][nc];
            }
#pragma unroll
            for (int mt = 0; mt < 4; mt++)
#pragma unroll
                for (int nt = 0; nt < 4; nt++)
                    mma_f16(acc[mt][nt], a[mt], b[nt], acc[mt][nt]);
        }
        __syncthreads();
    }

#pragma unroll
    for (int mt = 0; mt < 4; mt++)
#pragma unroll
        for (int nt = 0; nt < 4; nt++) {
            int c = col0 + wn * 32 + nt * 8 + 2 * tq;
            int h = c >> 6, d = c & 63;
#pragma unroll
            for (int half = 0; half < 2; half++) {
                int m = row0 + wm * 64 + mt * 16 + g + half * 8;
                int bi = m >> 11, n = m & 2047;
                *(unsigned*)&Y[(((size_t)(bi * HEADS + h) * SEQ + n) << 6) + d] =
                    f2h2(acc[mt][nt][half * 2], acc[mt][nt][half * 2 + 1]);
            }
        }
}

// ---------------- partial RoPE (fp16 data, f32 math) ----------------
__global__ void rope_kernel(const float* __restrict__ rope) {
    int idx = blockIdx.x * blockDim.x + threadIdx.x;
    if (idx >= BH * SEQ * 16) return;
    int p = idx & 15;
    int n = (idx >> 4) & (SEQ - 1);
    int z = idx >> 15;
    size_t base = ((size_t)z * SEQ + n) * DH;
    float r1 = rope[n * ROT + p];
    float r2 = rope[n * ROT + p + 16];
    float c1 = cosf(r1), s1 = sinf(r1);
    float c2 = cosf(r2), s2 = sinf(r2);
    __half* arrs[3] = {g_Q, g_K, g_V};
#pragma unroll
    for (int a = 0; a < 3; a++) {
        float t0 = __half2float(arrs[a][base + p]);
        float t1 = __half2float(arrs[a][base + p + 16]);
        arrs[a][base + p]      = __float2half(t0 * c1 - t1 * s1);
        arrs[a][base + p + 16] = __float2half(t1 * c2 + t0 * s2);
    }
}

// ================= fused flash attention (cp.async pipelined) ===============
// One CTA per (z, 128-row i-block). 8 warps 2(m)x4(n).
// smem rows: 64 halves padded to 72 (144 B) -> conflict-free.
#define RB 144   // row bytes
__global__ __launch_bounds__(256) void fused_attn(float* __restrict__ S) {
    extern __shared__ char smraw[];
    uint32_t sb = smem_u32(smraw);
    // layout: Q 18432 | K0 18432 | K1 18432 | V0 18432 | V1 18432 | inv 512 | part 2048
    uint32_t qb = sb, kb0 = sb + 18432, vb0 = sb + 55296;
    unsigned (*Qs)[36]  = (unsigned (*)[36])smraw;
    unsigned (*Ksm)[36] = (unsigned (*)[36])(smraw + 18432);   // 2 bufs: [buf*128+row]
    float* inv_s        = (float*)(smraw + 92160);
    float (*part)[4]    = (float (*)[4])(smraw + 92672);
    float (*obuf)[66]   = (float (*)[66])smraw;                // overlay (33792 B)

    int t = threadIdx.x;
    int w = t >> 5, lane = t & 31, g = lane >> 2, tq = lane & 3;
    int wm = w & 1, wn = w >> 1;
    int z = blockIdx.y;
    int i0 = blockIdx.x * 128;
    const __half* Qb = g_Q + (size_t)z * SEQ * DH;
    const __half* Kb = g_K + (size_t)z * SEQ * DH;
    const __half* Vb = g_V + (size_t)z * SEQ * DH;
    float* Sb = S + (size_t)z * SEQ * SEQ;

    // per-thread chunk coords (4 chunks of 16B per 128x64-half tile)
    int crow[4], cch[4];
#pragma unroll
    for (int s = 0; s < 4; s++) {
        int idx = t + s * 256;
        crow[s] = idx >> 3; cch[s] = (idx & 7) * 16;   // byte offset in row
    }

    // ---- issue Q + K(0) ----
#pragma unroll
    for (int s = 0; s < 4; s++) {
        CPA16(qb + crow[s] * RB + cch[s],
              (const char*)(Qb + (size_t)(i0 + crow[s]) * DH) + cch[s]);
        CPA16(kb0 + crow[s] * RB + cch[s],
              (const char*)(Kb + (size_t)crow[s] * DH) + cch[s]);
    }
    CPA_COMMIT();

    // ======== PASS 1: row sums ========
    float rsum[4][2];
#pragma unroll
    for (int i = 0; i < 4; i++) { rsum[i][0] = 0.f; rsum[i][1] = 0.f; }

    for (int p = 0; p < 16; p++) {
        int cur = p & 1;
        if (p + 1 < 16) {
            uint32_t kdst = kb0 + ((p + 1) & 1) * 18432;
            const __half* ksrc = Kb + (size_t)(p + 1) * 128 * DH;
#pragma unroll
            for (int s = 0; s < 4; s++)
                CPA16(kdst + crow[s] * RB + cch[s],
                      (const char*)(ksrc + (size_t)crow[s] * DH) + cch[s]);
            CPA_COMMIT();
            CPA_WAIT(1);
        } else {
            CPA_WAIT(0);
        }
        __syncthreads();

        float acc[4][4][4];
#pragma unroll
        for (int i = 0; i < 4; i++)
#pragma unroll
            for (int j = 0; j < 4; j++)
#pragma unroll
                for (int r = 0; r < 4; r++) acc[i][j][r] = 0.f;

#pragma unroll
        for (int ks = 0; ks < 4; ks++) {
            int kbq = ks * 8;
            unsigned a[4][4], b[4][2];
#pragma unroll
            for (int mt = 0; mt < 4; mt++) {
                int mr = wm * 64 + mt * 16 + g;
                a[mt][0] = Qs[mr][kbq + tq];       a[mt][1] = Qs[mr + 8][kbq + tq];
                a[mt][2] = Qs[mr][kbq + tq + 4];   a[mt][3] = Qs[mr + 8][kbq + tq + 4];
            }
#pragma unroll
            for (int nt = 0; nt < 4; nt++) {
                int nr = cur * 128 + wn * 32 + nt * 8 + g;
                b[nt][0] = Ksm[nr][kbq + tq];      b[nt][1] = Ksm[nr][kbq + tq + 4];
            }
#pragma unroll
            for (int mt = 0; mt < 4; mt++)
#pragma unroll
                for (int nt = 0; nt < 4; nt++)
                    mma_f16(acc[mt][nt], a[mt], b[nt], acc[mt][nt]);
        }
#pragma unroll
        for (int mt = 0; mt < 4; mt++)
#pragma unroll
            for (int nt = 0; nt < 4; nt++) {
                rsum[mt][0] += __expf(acc[mt][nt][0] * 0.125f) + __expf(acc[mt][nt][1] * 0.125f);
                rsum[mt][1] += __expf(acc[mt][nt][2] * 0.125f) + __expf(acc[mt][nt][3] * 0.125f);
            }
        __syncthreads();
    }

#pragma unroll
    for (int mt = 0; mt < 4; mt++)
#pragma unroll
        for (int half = 0; half < 2; half++) {
            float r = rsum[mt][half];
            r += __shfl_xor_sync(0xffffffffu, r, 1);
            r += __shfl_xor_sync(0xffffffffu, r, 2);
            if (tq == 0) part[wm * 64 + mt * 16 + half * 8 + g][wn] = r;
        }
    __syncthreads();
    if (t < 128) inv_s[t] = 1.f / (part[t][0] + part[t][1] + part[t][2] + part[t][3]);

    // ---- issue K(0)+V(0) for pass 2 ----
#pragma unroll
    for (int s = 0; s < 4; s++) {
        CPA16(kb0 + crow[s] * RB + cch[s],
              (const char*)(Kb + (size_t)crow[s] * DH) + cch[s]);
        CPA16(vb0 + crow[s] * RB + cch[s],
              (const char*)(Vb + (size_t)crow[s] * DH) + cch[s]);
    }
    CPA_COMMIT();

    // ======== PASS 2 ========
    float accO[4][8][4];
#pragma unroll
    for (int i = 0; i < 4; i++)
#pragma unroll
        for (int j = 0; j < 8; j++)
#pragma unroll
            for (int r = 0; r < 4; r++) accO[i][j][r] = 0.f;

    for (int p = 0; p < 16; p++) {
        int cur = p & 1;
        if (p + 1 < 16) {
            uint32_t kdst = kb0 + ((p + 1) & 1) * 18432;
            uint32_t vdst = vb0 + ((p + 1) & 1) * 18432;
            const __half* ksrc = Kb + (size_t)(p + 1) * 128 * DH;
            const __half* vsrc = Vb + (size_t)(p + 1) * 128 * DH;
#pragma unroll
            for (int s = 0; s < 4; s++) {
                CPA16(kdst + crow[s] * RB + cch[s],
                      (const char*)(ksrc + (size_t)crow[s] * DH) + cch[s]);
                CPA16(vdst + crow[s] * RB + cch[s],
                      (const char*)(vsrc + (size_t)crow[s] * DH) + cch[s]);
            }
            CPA_COMMIT();
            CPA_WAIT(1);
        } else {
            CPA_WAIT(0);
        }
        __syncthreads();

        float acc[4][4][4];
#pragma unroll
        for (int i = 0; i < 4; i++)
#pragma unroll
            for (int j = 0; j < 4; j++)
#pragma unroll
                for (int r = 0; r < 4; r++) acc[i][j][r] = 0.f;

#pragma unroll
        for (int ks = 0; ks < 4; ks++) {
            int kbq = ks * 8;
            unsigned a[4][4], b[4][2];
#pragma unroll
            for (int mt = 0; mt < 4; mt++) {
                int mr = wm * 64 + mt * 16 + g;
                a[mt][0] = Qs[mr][kbq + tq];       a[mt][1] = Qs[mr + 8][kbq + tq];
                a[mt][2] = Qs[mr][kbq + tq + 4];   a[mt][3] = Qs[mr + 8][kbq + tq + 4];
            }
#pragma unroll
            for (int nt = 0; nt < 4; nt++) {
                int nr = cur * 128 + wn * 32 + nt * 8 + g;
                b[nt][0] = Ksm[nr][kbq + tq];      b[nt][1] = Ksm[nr][kbq + tq + 4];
            }
#pragma unroll
            for (int mt = 0; mt < 4; mt++)
#pragma unroll
                for (int nt = 0; nt < 4; nt++)
                    mma_f16(acc[mt][nt], a[mt], b[nt], acc[mt][nt]);
        }

        int j0 = p * 128;
#pragma unroll
        for (int mt = 0; mt < 4; mt++) {
            int mr0 = wm * 64 + mt * 16 + g;
            float iv0 = inv_s[mr0];
            float iv1 = inv_s[mr0 + 8];
#pragma unroll
            for (int nt = 0; nt < 4; nt++) {
                acc[mt][nt][0] = __expf(acc[mt][nt][0] * 0.125f) * iv0;
                acc[mt][nt][1] = __expf(acc[mt][nt][1] * 0.125f) * iv0;
                acc[mt][nt][2] = __expf(acc[mt][nt][2] * 0.125f) * iv1;
                acc[mt][nt][3] = __expf(acc[mt][nt][3] * 0.125f) * iv1;
                int c = j0 + wn * 32 + nt * 8 + 2 * tq;
                stcs2(&Sb[(size_t)(i0 + mr0) * SEQ + c],     acc[mt][nt][0], acc[mt][nt][1]);
                stcs2(&Sb[(size_t)(i0 + mr0 + 8) * SEQ + c], acc[mt][nt][2], acc[mt][nt][3]);
            }
        }

        // PV: P frags from acc; V frags via ldmatrix.x4.trans from row-major Vs
        uint32_t vbase = vb0 + cur * 18432;
#pragma unroll
        for (int s = 0; s < 2; s++) {
            unsigned aP[4][4];
#pragma unroll
            for (int mt = 0; mt < 4; mt++) {
                aP[mt][0] = f2h2(acc[mt][2*s][0],   acc[mt][2*s][1]);
                aP[mt][1] = f2h2(acc[mt][2*s][2],   acc[mt][2*s][3]);
                aP[mt][2] = f2h2(acc[mt][2*s+1][0], acc[mt][2*s+1][1]);
                aP[mt][3] = f2h2(acc[mt][2*s+1][2], acc[mt][2*s+1][3]);
            }
#pragma unroll
            for (int nt2 = 0; nt2 < 4; nt2++) {
                unsigned r0, r1, r2, r3;
                uint32_t addr = vbase + (wn * 32 + s * 16 + (lane & 15)) * RB
                              + (nt2 * 16 + (lane >> 4) * 8) * 2;
                ldsm_x4_t(r0, r1, r2, r3, addr);
                unsigned b0[2] = {r0, r1}, b1[2] = {r2, r3};
#pragma unroll
                for (int mt = 0; mt < 4; mt++) {
                    mma_f16(accO[mt][2*nt2],     aP[mt], b0, accO[mt][2*nt2]);
                    mma_f16(accO[mt][2*nt2 + 1], aP[mt], b1, accO[mt][2*nt2 + 1]);
                }
            }
        }
        __syncthreads();
    }

    // ---- cross-warp O reduce (over wn) via smem ----
    __syncthreads();
#pragma unroll
    for (int p = 0; p < 4; p++) {
        if (wn == p) {
#pragma unroll
            for (int mt = 0; mt < 4; mt++) {
                int r0 = wm * 64 + mt * 16 + g;
#pragma unroll
                for (int nt = 0; nt < 8; nt++) {
                    int c = nt * 8 + 2 * tq;
                    if (p == 0) {
                        *(float2*)&obuf[r0][c]     = make_float2(accO[mt][nt][0], accO[mt][nt][1]);
                        *(float2*)&obuf[r0 + 8][c] = make_float2(accO[mt][nt][2], accO[mt][nt][3]);
                    } else {
                        float2 o0 = *(float2*)&obuf[r0][c];
                        float2 o1 = *(float2*)&obuf[r0 + 8][c];
                        o0.x += accO[mt][nt][0]; o0.y += accO[mt][nt][1];
                        o1.x += accO[mt][nt][2]; o1.y += accO[mt][nt][3];
                        *(float2*)&obuf[r0][c] = o0;
                        *(float2*)&obuf[r0 + 8][c] = o1;
                    }
                }
            }
        }
        __syncthreads();
    }

    // write O (half): [b, n, h*64+d]
    int bi = z >> 4, h = z & 15;
#pragma unroll
    for (int it = 0; it < 8; it++) {
        int idx = t + it * 256;
        int m = idx >> 4, c4 = (idx & 15) * 4;
        uint2 v = make_uint2(f2h2(obuf[m][c4], obuf[m][c4 + 1]),
                             f2h2(obuf[m][c4 + 2], obuf[m][c4 + 3]));
        *(uint2*)&g_O[((size_t)bi * SEQ + i0 + m) * DIMD + h * 64 + c4] = v;
    }
}

// ============ final GEMM: out = g_O(half) @ Wo + bo + x ====================
__global__ __launch_bounds__(256) void final_gemm_f16(
    const float* __restrict__ W, const float* __restrict__ bo,
    const float* __restrict__ resid, float* __restrict__ Y)
{
    __shared__ unsigned As[128][20];
    __shared__ unsigned Bs[16][136];
    int t = threadIdx.x;
    int w = t >> 5, lane = t & 31, g = lane >> 2, tq = lane & 3;
    int wm = w & 1, wn = w >> 1;
    int row0 = blockIdx.y * 128, col0 = blockIdx.x * 128;

    float acc[4][4][4];
#pragma unroll
    for (int i = 0; i < 4; i++)
#pragma unroll
        for (int j = 0; j < 4; j++)
#pragma unroll
            for (int r = 0; r < 4; r++) acc[i][j][r] = 0.f;

    int arow[2], akg[2], bkp[2], bc4[2];
#pragma unroll
    for (int s = 0; s < 2; s++) {
        int idx = t + s * 256;
        arow[s] = idx >> 2;  akg[s] = (idx & 3) * 8;   // halves
        bkp[s]  = idx >> 5;  bc4[s] = (idx & 31) * 4;
    }
    uint4 xa[2]; float4 wb[2][2];
#pragma unroll
    for (int s = 0; s < 2; s++) {
        xa[s] = *(const uint4*)(g_O + (size_t)(row0 + arow[s]) * DIMD + akg[s]);
        const float* pb = W + (size_t)(2 * bkp[s]) * DIMD + col0 + bc4[s];
        wb[s][0] = *(const float4*)pb; wb[s][1] = *(const float4*)(pb + DIMD);
    }

    for (int p = 0; p < 32; p++) {
#pragma unroll
        for (int s = 0; s < 2; s++) {
            *(uint4*)&As[arow[s]][(akg[s] >> 1)] = xa[s];
            *(uint4*)&Bs[bkp[s]][bc4[s]] = make_uint4(
                f2h2(wb[s][0].x, wb[s][1].x), f2h2(wb[s][0].y, wb[s][1].y),
                f2h2(wb[s][0].z, wb[s][1].z), f2h2(wb[s][0].w, wb[s][1].w));
        }
        __syncthreads();
        if (p + 1 < 32) {
            int k0 = (p + 1) * 32;
#pragma unroll
            for (int s = 0; s < 2; s++) {
                xa[s] = *(const uint4*)(g_O + (size_t)(row0 + arow[s]) * DIMD + k0 + akg[s]);
                const float* pb = W + (size_t)(k0 + 2 * bkp[s]) * DIMD + col0 + bc4[s];
                wb[s][0] = *(const float4*)pb; wb[s][1] = *(const float4*)(pb + DIMD);
            }
        }
#pragma unroll
        for (int ks = 0; ks < 2; ks++) {
            int kb = ks * 8;
            unsigned a[4][4], b[4][2];
#pragma unroll
            for (int mt = 0; mt < 4; mt++) {
                int mr = wm * 64 + mt * 16 + g;
                a[mt][0] = As[mr][kb + tq];       a[mt][1] = As[mr + 8][kb + tq];
                a[mt][2] = As[mr][kb + tq + 4];   a[mt][3] = As[mr + 8][kb + tq + 4];
            }
#pragma unroll
            for (int nt = 0; nt < 4; nt++) {
                int nc = wn * 32 + nt * 8 + g;
                b[nt][0] = Bs[kb + tq][nc];       b[nt][1] = Bs[kb + tq + 4][nc];
            }
#pragma unroll
            for (int mt = 0; mt < 4; mt++)
#pragma unroll
                for (int nt = 0; nt < 4; nt++)
                    mma_f16(acc[mt][nt], a[mt], b[nt], acc[mt][nt]);
        }
        __syncthreads();
    }

#pragma unroll
    for (int mt = 0; mt < 4; mt++)
#pragma unroll
        for (int nt = 0; nt < 4; nt++) {
            int c = col0 + wn * 32 + nt * 8 + 2 * tq;
#pragma unroll
            for (int half = 0; half < 2; half++) {
                int m = row0 + wm * 64 + mt * 16 + g + half * 8;
                float2 val = make_float2(acc[mt][nt][half * 2], acc[mt][nt][half * 2 + 1]);
                float2 bv = *(const float2*)&bo[c];
                float2 rv = *(const float2*)&resid[(size_t)m * DIMD + c];
                val.x += bv.x + rv.x;
                val.y += bv.y + rv.y;
                *(float2*)&Y[(size_t)m * DIMD + c] = val;
            }
        }
}

// ---------------------------- launcher -------------------------------------
extern "C" void kernel_launch(void* const* d_in, const int* in_sizes, int n_in,
                              void* d_out, int out_size) {
    const float* x    = (const float*)d_in[0];
    const float* rope = (const float*)d_in[1];
    const float* Wq   = (const float*)d_in[2];
    const float* Wk   = (const float*)d_in[3];
    const float* Wv   = (const float*)d_in[4];
    const float* Wo   = (const float*)d_in[5];
    const float* bo   = (const float*)d_in[6];

    float* out  = (float*)d_out;
    float* attn = out + OUT_ELEMS;

    const int FA_SMEM = 94720;
    cudaFuncSetAttribute(fused_attn, cudaFuncAttributeMaxDynamicSharedMemorySize, FA_SMEM);

    proj3_f16<<<dim3(8, 64, 3), 256>>>(x, Wq, Wk, Wv);

    rope_kernel<<<(BH * SEQ * 16) / 256, 256>>>(rope);

    fused_attn<<<dim3(16, 64), 256, FA_SMEM>>>(attn);

    final_gemm_f16<<<dim3(8, 64), 256>>>(Wo, bo, x, out);
}

// round 9
// speedup vs baseline: 5.6387x; 1.0771x over previous
#include <cuda_runtime.h>
#include <cuda_fp16.h>
#include <math.h>
#include <stdint.h>

#define BB     4
#define SEQ    2048
#define DIMD   1024
#define HEADS  16
#define DH     64
#define ROT    32
#define BH     (BB*HEADS)          // 64
#define MROWS  (BB*SEQ)            // 8192
#define OUT_ELEMS ((size_t)MROWS*DIMD)

// ---------------- scratch (fp16) ----------------
__device__ __half g_Q[(size_t)BH*SEQ*DH];
__device__ __half g_K[(size_t)BH*SEQ*DH];
__device__ __half g_V[(size_t)BH*SEQ*DH];
__device__ __half g_O[(size_t)MROWS*DIMD];
__device__ __half g_X[(size_t)MROWS*DIMD];        // x in fp16
__device__ __half g_Wh[(size_t)4*DIMD*DIMD];      // Wq,Wk,Wv,Wo in fp16

// ---------------- helpers ----------------
__device__ __forceinline__ unsigned f2h2(float a, float b) {
    unsigned u;
    asm("cvt.rn.f16x2.f32 %0, %2, %1;" : "=r"(u) : "f"(a), "f"(b));
    return u;
}
__device__ __forceinline__ uint32_t smem_u32(const void* p) {
    uint32_t a;
    asm("{ .reg .u64 t; cvta.to.shared.u64 t, %1; cvt.u32.u64 %0, t; }" : "=r"(a) : "l"(p));
    return a;
}
__device__ __forceinline__ void mma_f16(float d[4], const unsigned a[4],
                                        const unsigned b[2], const float c[4]) {
    asm volatile(
        "mma.sync.aligned.m16n8k16.row.col.f32.f16.f16.f32 "
        "{%0,%1,%2,%3}, {%4,%5,%6,%7}, {%8,%9}, {%10,%11,%12,%13};"
        : "=f"(d[0]), "=f"(d[1]), "=f"(d[2]), "=f"(d[3])
        : "r"(a[0]), "r"(a[1]), "r"(a[2]), "r"(a[3]),
          "r"(b[0]), "r"(b[1]),
          "f"(c[0]), "f"(c[1]), "f"(c[2]), "f"(c[3]));
}
__device__ __forceinline__ void ldsm_x4(unsigned& r0, unsigned& r1,
                                        unsigned& r2, unsigned& r3, uint32_t a) {
    asm volatile("ldmatrix.sync.aligned.m8n8.x4.shared.b16 {%0,%1,%2,%3}, [%4];"
                 : "=r"(r0), "=r"(r1), "=r"(r2), "=r"(r3) : "r"(a));
}
__device__ __forceinline__ void ldsm_x4_t(unsigned& r0, unsigned& r1,
                                          unsigned& r2, unsigned& r3, uint32_t a) {
    asm volatile("ldmatrix.sync.aligned.m8n8.x4.trans.shared.b16 {%0,%1,%2,%3}, [%4];"
                 : "=r"(r0), "=r"(r1), "=r"(r2), "=r"(r3) : "r"(a));
}
#define CPA16(d, s)   asm volatile("cp.async.ca.shared.global [%0], [%1], 16;" :: "r"(d), "l"(s))
#define CPA_COMMIT()  asm volatile("cp.async.commit_group;" ::: "memory")
#define CPA_WAIT(n)   asm volatile("cp.async.wait_group %0;" :: "n"(n) : "memory")
__device__ __forceinline__ void stcs2(float* p, float x, float y) {
    asm volatile("st.global.cs.v2.f32 [%0], {%1,%2};" :: "l"(p), "f"(x), "f"(y));
}

// ---------------- f32 -> f16 conversion (x + 4 weights) ----------------
__global__ void convert_half(const float* __restrict__ x,
                             const float* __restrict__ Wq, const float* __restrict__ Wk,
                             const float* __restrict__ Wv, const float* __restrict__ Wo) {
    size_t i = (size_t)blockIdx.x * blockDim.x + threadIdx.x;   // float4 index
    const size_t XN = OUT_ELEMS / 4;         // 2M
    const size_t WN = (size_t)DIMD * DIMD / 4;
    const float* src; __half* dst; size_t off;
    if (i < XN)                { src = x;  dst = g_X;               off = i; }
    else if (i < XN + WN)      { src = Wq; dst = g_Wh;              off = i - XN; }
    else if (i < XN + 2 * WN)  { src = Wk; dst = g_Wh + WN * 4;     off = i - XN - WN; }
    else if (i < XN + 3 * WN)  { src = Wv; dst = g_Wh + 2 * WN * 4; off = i - XN - 2 * WN; }
    else                       { src = Wo; dst = g_Wh + 3 * WN * 4; off = i - XN - 3 * WN; }
    float4 v = *(const float4*)(src + off * 4);
    *(uint2*)(dst + off * 4) = make_uint2(f2h2(v.x, v.y), f2h2(v.z, v.w));
}

// ============ pipelined fp16 GEMM (cp.async + ldmatrix) =====================
// A [8192 or MROWS,1024] half rm, B [1024,1024] half rm. Tile 128x128xK32.
// MODE 0: proj (blockIdx.z selects W/out, head-major half out)
// MODE 1: final (f32 out + bias + resid)
#define A_STRIDE 80    // bytes per 32-half A row (64 + 16 pad)
#define B_STRIDE 272   // bytes per 128-half B row (256 + 16 pad)
template <int MODE>
__global__ __launch_bounds__(256) void gemm_pipe(
    const __half* __restrict__ Aglob, const __half* __restrict__ Wbase,
    const float* __restrict__ bo, const float* __restrict__ resid,
    float* __restrict__ Yf)
{
    extern __shared__ char sm[];
    uint32_t sb = smem_u32(sm);
    uint32_t Ab[2] = {sb, sb + 10240};
    uint32_t Bb[2] = {sb + 20480, sb + 20480 + 8704};

    int t = threadIdx.x, lane = t & 31, w = t >> 5;
    int g = lane >> 2, tq = lane & 3;
    int wm = w & 1, wn = w >> 1;
    int row0 = blockIdx.y * 128, col0 = blockIdx.x * 128;

    const __half* Bh;
    __half* Yh = nullptr;
    if (MODE == 0) {
        int z = blockIdx.z;
        Bh = Wbase + (size_t)z * DIMD * DIMD;
        Yh = (z == 0) ? g_Q : (z == 1) ? g_K : g_V;
    } else {
        Bh = Wbase;
    }

    float acc[4][4][4];
#pragma unroll
    for (int i = 0; i < 4; i++)
#pragma unroll
        for (int j = 0; j < 4; j++)
#pragma unroll
            for (int r = 0; r < 4; r++) acc[i][j][r] = 0.f;

    int ar[2], ac[2], br[2], bc[2];
#pragma unroll
    for (int s = 0; s < 2; s++) {
        int idx = t + s * 256;
        ar[s] = idx >> 2;  ac[s] = (idx & 3) * 16;     // A: 4 chunks/row
        br[s] = idx >> 4;  bc[s] = (idx & 15) * 16;    // B: 16 chunks/row
    }

#define ISSUE(p) do { \
    int _buf = (p) & 1; int _k0 = (p) * 32; \
    _Pragma("unroll") \
    for (int s = 0; s < 2; s++) { \
        CPA16(Ab[_buf] + ar[s] * A_STRIDE + ac[s], \
              (const char*)(Aglob + (size_t)(row0 + ar[s]) * DIMD + _k0) + ac[s]); \
        CPA16(Bb[_buf] + br[s] * B_STRIDE + bc[s], \
              (const char*)(Bh + (size_t)(_k0 + br[s]) * DIMD + col0) + bc[s]); \
    } \
} while (0)

    ISSUE(0); CPA_COMMIT();

    for (int p = 0; p < 32; p++) {
        if (p + 1 < 32) { ISSUE(p + 1); CPA_COMMIT(); CPA_WAIT(1); }
        else            { CPA_WAIT(0); }
        __syncthreads();
        int buf = p & 1;
#pragma unroll
        for (int ks = 0; ks < 2; ks++) {
            int kh = ks * 16;
            unsigned a[4][4], b[4][2];
#pragma unroll
            for (int mt = 0; mt < 4; mt++) {
                uint32_t addr = Ab[buf] + (wm * 64 + mt * 16 + (lane & 15)) * A_STRIDE
                              + (kh + (lane >> 4) * 8) * 2;
                ldsm_x4(a[mt][0], a[mt][1], a[mt][2], a[mt][3], addr);
            }
#pragma unroll
            for (int nt2 = 0; nt2 < 2; nt2++) {
                unsigned r0, r1, r2, r3;
                uint32_t addr = Bb[buf] + (kh + (lane & 15)) * B_STRIDE
                              + (wn * 32 + nt2 * 16 + (lane >> 4) * 8) * 2;
                ldsm_x4_t(r0, r1, r2, r3, addr);
                b[nt2 * 2][0] = r0;     b[nt2 * 2][1] = r1;
                b[nt2 * 2 + 1][0] = r2; b[nt2 * 2 + 1][1] = r3;
            }
#pragma unroll
            for (int mt = 0; mt < 4; mt++)
#pragma unroll
                for (int nt = 0; nt < 4; nt++)
                    mma_f16(acc[mt][nt], a[mt], b[nt], acc[mt][nt]);
        }
        __syncthreads();
    }
#undef ISSUE

#pragma unroll
    for (int mt = 0; mt < 4; mt++)
#pragma unroll
        for (int nt = 0; nt < 4; nt++) {
            int c = col0 + wn * 32 + nt * 8 + 2 * tq;
#pragma unroll
            for (int half = 0; half < 2; half++) {
                int m = row0 + wm * 64 + mt * 16 + g + half * 8;
                float2 val = make_float2(acc[mt][nt][half * 2], acc[mt][nt][half * 2 + 1]);
                if (MODE == 0) {
                    int bi = m >> 11, n = m & 2047, h = c >> 6, d = c & 63;
                    *(unsigned*)&Yh[(((size_t)(bi * HEADS + h) * SEQ + n) << 6) + d] =
                        f2h2(val.x, val.y);
                } else {
                    float2 bv = *(const float2*)&bo[c];
                    float2 rv = *(const float2*)&resid[(size_t)m * DIMD + c];
                    val.x += bv.x + rv.x;
                    val.y += bv.y + rv.y;
                    *(float2*)&Yf[(size_t)m * DIMD + c] = val;
                }
            }
        }
}

// ---------------- partial RoPE (fp16 data, f32 math) ----------------
__global__ void rope_kernel(const float* __restrict__ rope) {
    int idx = blockIdx.x * blockDim.x + threadIdx.x;
    if (idx >= BH * SEQ * 16) return;
    int p = idx & 15;
    int n = (idx >> 4) & (SEQ - 1);
    int z = idx >> 15;
    size_t base = ((size_t)z * SEQ + n) * DH;
    float r1 = rope[n * ROT + p];
    float r2 = rope[n * ROT + p + 16];
    float c1 = cosf(r1), s1 = sinf(r1);
    float c2 = cosf(r2), s2 = sinf(r2);
    __half* arrs[3] = {g_Q, g_K, g_V};
#pragma unroll
    for (int a = 0; a < 3; a++) {
        float t0 = __half2float(arrs[a][base + p]);
        float t1 = __half2float(arrs[a][base + p + 16]);
        arrs[a][base + p]      = __float2half(t0 * c1 - t1 * s1);
        arrs[a][base + p + 16] = __float2half(t1 * c2 + t0 * s2);
    }
}

// ================= fused flash attention (cp.async pipelined) ===============
#define RB 144   // row bytes (64 halves + pad)
__global__ __launch_bounds__(256) void fused_attn(float* __restrict__ S) {
    extern __shared__ char smraw[];
    uint32_t sb = smem_u32(smraw);
    uint32_t qb = sb, kb0 = sb + 18432, vb0 = sb + 55296;
    unsigned (*Qs)[36]  = (unsigned (*)[36])smraw;
    unsigned (*Ksm)[36] = (unsigned (*)[36])(smraw + 18432);
    float* inv_s        = (float*)(smraw + 92160);
    float (*part)[4]    = (float (*)[4])(smraw + 92672);
    float (*obuf)[66]   = (float (*)[66])smraw;

    int t = threadIdx.x;
    int w = t >> 5, lane = t & 31, g = lane >> 2, tq = lane & 3;
    int wm = w & 1, wn = w >> 1;
    int z = blockIdx.y;
    int i0 = blockIdx.x * 128;
    const __half* Qb = g_Q + (size_t)z * SEQ * DH;
    const __half* Kb = g_K + (size_t)z * SEQ * DH;
    const __half* Vb = g_V + (size_t)z * SEQ * DH;
    float* Sb = S + (size_t)z * SEQ * SEQ;

    int crow[4], cch[4];
#pragma unroll
    for (int s = 0; s < 4; s++) {
        int idx = t + s * 256;
        crow[s] = idx >> 3; cch[s] = (idx & 7) * 16;
    }

#pragma unroll
    for (int s = 0; s < 4; s++) {
        CPA16(qb + crow[s] * RB + cch[s],
              (const char*)(Qb + (size_t)(i0 + crow[s]) * DH) + cch[s]);
        CPA16(kb0 + crow[s] * RB + cch[s],
              (const char*)(Kb + (size_t)crow[s] * DH) + cch[s]);
    }
    CPA_COMMIT();

    float rsum[4][2];
#pragma unroll
    for (int i = 0; i < 4; i++) { rsum[i][0] = 0.f; rsum[i][1] = 0.f; }

    for (int p = 0; p < 16; p++) {
        int cur = p & 1;
        if (p + 1 < 16) {
            uint32_t kdst = kb0 + ((p + 1) & 1) * 18432;
            const __half* ksrc = Kb + (size_t)(p + 1) * 128 * DH;
#pragma unroll
            for (int s = 0; s < 4; s++)
                CPA16(kdst + crow[s] * RB + cch[s],
                      (const char*)(ksrc + (size_t)crow[s] * DH) + cch[s]);
            CPA_COMMIT();
            CPA_WAIT(1);
        } else {
            CPA_WAIT(0);
        }
        __syncthreads();

        float acc[4][4][4];
#pragma unroll
        for (int i = 0; i < 4; i++)
#pragma unroll
            for (int j = 0; j < 4; j++)
#pragma unroll
                for (int r = 0; r < 4; r++) acc[i][j][r] = 0.f;

#pragma unroll
        for (int ks = 0; ks < 4; ks++) {
            int kbq = ks * 8;
            unsigned a[4][4], b[4][2];
#pragma unroll
            for (int mt = 0; mt < 4; mt++) {
                int mr = wm * 64 + mt * 16 + g;
                a[mt][0] = Qs[mr][kbq + tq];       a[mt][1] = Qs[mr + 8][kbq + tq];
                a[mt][2] = Qs[mr][kbq + tq + 4];   a[mt][3] = Qs[mr + 8][kbq + tq + 4];
            }
#pragma unroll
            for (int nt = 0; nt < 4; nt++) {
                int nr = cur * 128 + wn * 32 + nt * 8 + g;
                b[nt][0] = Ksm[nr][kbq + tq];      b[nt][1] = Ksm[nr][kbq + tq + 4];
            }
#pragma unroll
            for (int mt = 0; mt < 4; mt++)
#pragma unroll
                for (int nt = 0; nt < 4; nt++)
                    mma_f16(acc[mt][nt], a[mt], b[nt], acc[mt][nt]);
        }
#pragma unroll
        for (int mt = 0; mt < 4; mt++)
#pragma unroll
            for (int nt = 0; nt < 4; nt++) {
                rsum[mt][0] += __expf(acc[mt][nt][0] * 0.125f) + __expf(acc[mt][nt][1] * 0.125f);
                rsum[mt][1] += __expf(acc[mt][nt][2] * 0.125f) + __expf(acc[mt][nt][3] * 0.125f);
            }
        __syncthreads();
    }

#pragma unroll
    for (int mt = 0; mt < 4; mt++)
#pragma unroll
        for (int half = 0; half < 2; half++) {
            float r = rsum[mt][half];
            r += __shfl_xor_sync(0xffffffffu, r, 1);
            r += __shfl_xor_sync(0xffffffffu, r, 2);
            if (tq == 0) part[wm * 64 + mt * 16 + half * 8 + g][wn] = r;
        }
    __syncthreads();
    if (t < 128) inv_s[t] = 1.f / (part[t][0] + part[t][1] + part[t][2] + part[t][3]);

#pragma unroll
    for (int s = 0; s < 4; s++) {
        CPA16(kb0 + crow[s] * RB + cch[s],
              (const char*)(Kb + (size_t)crow[s] * DH) + cch[s]);
        CPA16(vb0 + crow[s] * RB + cch[s],
              (const char*)(Vb + (size_t)crow[s] * DH) + cch[s]);
    }
    CPA_COMMIT();

    float accO[4][8][4];
#pragma unroll
    for (int i = 0; i < 4; i++)
#pragma unroll
        for (int j = 0; j < 8; j++)
#pragma unroll
            for (int r = 0; r < 4; r++) accO[i][j][r] = 0.f;

    for (int p = 0; p < 16; p++) {
        int cur = p & 1;
        if (p + 1 < 16) {
            uint32_t kdst = kb0 + ((p + 1) & 1) * 18432;
            uint32_t vdst = vb0 + ((p + 1) & 1) * 18432;
            const __half* ksrc = Kb + (size_t)(p + 1) * 128 * DH;
            const __half* vsrc = Vb + (size_t)(p + 1) * 128 * DH;
#pragma unroll
            for (int s = 0; s < 4; s++) {
                CPA16(kdst + crow[s] * RB + cch[s],
                      (const char*)(ksrc + (size_t)crow[s] * DH) + cch[s]);
                CPA16(vdst + crow[s] * RB + cch[s],
                      (const char*)(vsrc + (size_t)crow[s] * DH) + cch[s]);
            }
            CPA_COMMIT();
            CPA_WAIT(1);
        } else {
            CPA_WAIT(0);
        }
        __syncthreads();

        float acc[4][4][4];
#pragma unroll
        for (int i = 0; i < 4; i++)
#pragma unroll
            for (int j = 0; j < 4; j++)
#pragma unroll
                for (int r = 0; r < 4; r++) acc[i][j][r] = 0.f;

#pragma unroll
        for (int ks = 0; ks < 4; ks++) {
            int kbq = ks * 8;
            unsigned a[4][4], b[4][2];
#pragma unroll
            for (int mt = 0; mt < 4; mt++) {
                int mr = wm * 64 + mt * 16 + g;
                a[mt][0] = Qs[mr][kbq + tq];       a[mt][1] = Qs[mr + 8][kbq + tq];
                a[mt][2] = Qs[mr][kbq + tq + 4];   a[mt][3] = Qs[mr + 8][kbq + tq + 4];
            }
#pragma unroll
            for (int nt = 0; nt < 4; nt++) {
                int nr = cur * 128 + wn * 32 + nt * 8 + g;
                b[nt][0] = Ksm[nr][kbq + tq];      b[nt][1] = Ksm[nr][kbq + tq + 4];
            }
#pragma unroll
            for (int mt = 0; mt < 4; mt++)
#pragma unroll
                for (int nt = 0; nt < 4; nt++)
                    mma_f16(acc[mt][nt], a[mt], b[nt], acc[mt][nt]);
        }

        int j0 = p * 128;
#pragma unroll
        for (int mt = 0; mt < 4; mt++) {
            int mr0 = wm * 64 + mt * 16 + g;
            float iv0 = inv_s[mr0];
            float iv1 = inv_s[mr0 + 8];
#pragma unroll
            for (int nt = 0; nt < 4; nt++) {
                acc[mt][nt][0] = __expf(acc[mt][nt][0] * 0.125f) * iv0;
                acc[mt][nt][1] = __expf(acc[mt][nt][1] * 0.125f) * iv0;
                acc[mt][nt][2] = __expf(acc[mt][nt][2] * 0.125f) * iv1;
                acc[mt][nt][3] = __expf(acc[mt][nt][3] * 0.125f) * iv1;
                int c = j0 + wn * 32 + nt * 8 + 2 * tq;
                stcs2(&Sb[(size_t)(i0 + mr0) * SEQ + c],     acc[mt][nt][0], acc[mt][nt][1]);
                stcs2(&Sb[(size_t)(i0 + mr0 + 8) * SEQ + c], acc[mt][nt][2], acc[mt][nt][3]);
            }
        }

        uint32_t vbase = vb0 + cur * 18432;
#pragma unroll
        for (int s = 0; s < 2; s++) {
            unsigned aP[4][4];
#pragma unroll
            for (int mt = 0; mt < 4; mt++) {
                aP[mt][0] = f2h2(acc[mt][2*s][0],   acc[mt][2*s][1]);
                aP[mt][1] = f2h2(acc[mt][2*s][2],   acc[mt][2*s][3]);
                aP[mt][2] = f2h2(acc[mt][2*s+1][0], acc[mt][2*s+1][1]);
                aP[mt][3] = f2h2(acc[mt][2*s+1][2], acc[mt][2*s+1][3]);
            }
#pragma unroll
            for (int nt2 = 0; nt2 < 4; nt2++) {
                unsigned r0, r1, r2, r3;
                uint32_t addr = vbase + (wn * 32 + s * 16 + (lane & 15)) * RB
                              + (nt2 * 16 + (lane >> 4) * 8) * 2;
                ldsm_x4_t(r0, r1, r2, r3, addr);
                unsigned b0[2] = {r0, r1}, b1[2] = {r2, r3};
#pragma unroll
                for (int mt = 0; mt < 4; mt++) {
                    mma_f16(accO[mt][2*nt2],     aP[mt], b0, accO[mt][2*nt2]);
                    mma_f16(accO[mt][2*nt2 + 1], aP[mt], b1, accO[mt][2*nt2 + 1]);
                }
            }
        }
        __syncthreads();
    }

    __syncthreads();
#pragma unroll
    for (int p = 0; p < 4; p++) {
        if (wn == p) {
#pragma unroll
            for (int mt = 0; mt < 4; mt++) {
                int r0 = wm * 64 + mt * 16 + g;
#pragma unroll
                for (int nt = 0; nt < 8; nt++) {
                    int c = nt * 8 + 2 * tq;
                    if (p == 0) {
                        *(float2*)&obuf[r0][c]     = make_float2(accO[mt][nt][0], accO[mt][nt][1]);
                        *(float2*)&obuf[r0 + 8][c] = make_float2(accO[mt][nt][2], accO[mt][nt][3]);
                    } else {
                        float2 o0 = *(float2*)&obuf[r0][c];
                        float2 o1 = *(float2*)&obuf[r0 + 8][c];
                        o0.x += accO[mt][nt][0]; o0.y += accO[mt][nt][1];
                        o1.x += accO[mt][nt][2]; o1.y += accO[mt][nt][3];
                        *(float2*)&obuf[r0][c] = o0;
                        *(float2*)&obuf[r0 + 8][c] = o1;
                    }
                }
            }
        }
        __syncthreads();
    }

    int bi = z >> 4, h = z & 15;
#pragma unroll
    for (int it = 0; it < 8; it++) {
        int idx = t + it * 256;
        int m = idx >> 4, c4 = (idx & 15) * 4;
        uint2 v = make_uint2(f2h2(obuf[m][c4], obuf[m][c4 + 1]),
                             f2h2(obuf[m][c4 + 2], obuf[m][c4 + 3]));
        *(uint2*)&g_O[((size_t)bi * SEQ + i0 + m) * DIMD + h * 64 + c4] = v;
    }
}

// ---------------------------- launcher -------------------------------------
extern "C" void kernel_launch(void* const* d_in, const int* in_sizes, int n_in,
                              void* d_out, int out_size) {
    const float* x    = (const float*)d_in[0];
    const float* rope = (const float*)d_in[1];
    const float* Wq   = (const float*)d_in[2];
    const float* Wk   = (const float*)d_in[3];
    const float* Wv   = (const float*)d_in[4];
    const float* Wo   = (const float*)d_in[5];
    const float* bo   = (const float*)d_in[6];

    float* out  = (float*)d_out;
    float* attn = out + OUT_ELEMS;

    __half *Xp, *Whp, *Op;
    cudaGetSymbolAddress((void**)&Xp,  g_X);
    cudaGetSymbolAddress((void**)&Whp, g_Wh);
    cudaGetSymbolAddress((void**)&Op,  g_O);

    const int FA_SMEM = 94720;
    const int GP_SMEM = 37888;
    cudaFuncSetAttribute(fused_attn, cudaFuncAttributeMaxDynamicSharedMemorySize, FA_SMEM);

    // convert x + weights to fp16 (12M elems -> 3M float4)
    convert_half<<<(int)((OUT_ELEMS / 4 + 4 * DIMD * DIMD / 4) / 256), 256>>>(x, Wq, Wk, Wv, Wo);

    gemm_pipe<0><<<dim3(8, 64, 3), 256, GP_SMEM>>>(Xp, Whp, nullptr, nullptr, nullptr);

    rope_kernel<<<(BH * SEQ * 16) / 256, 256>>>(rope);

    fused_attn<<<dim3(16, 64), 256, FA_SMEM>>>(attn);

    gemm_pipe<1><<<dim3(8, 64), 256, GP_SMEM>>>(Op, Whp + 3 * (size_t)DIMD * DIMD, bo, x, out);
}